// round 5
// baseline (speedup 1.0000x reference)
#include <cuda_runtime.h>
#include <cuda_bf16.h>
#include <math.h>
#include <stdint.h>

#define Lc   6
#define Bc   32
#define Tc   256
#define SAc  512
#define STc  128
#define Dc   1024
#define Hc   16
#define HDc  64
#define DFFc 4096
#define OUTc 3
#define MTc  (Bc*Tc)     // 8192
#define MAc  (Bc*SAc)    // 16384
#define MSc  (Bc*STc)    // 4096
#define DDc  (Dc*Dc)
#define WPLc (8*DDc + Dc*DFFc + DFFc*Dc)   // bf16 elems per layer

// ---------------- scratch (static device globals; no allocation) ----------------
__device__ float g_x [MTc*Dc];
__device__ float g_q [MTc*Dc];
__device__ float g_ks[MTc*Dc];
__device__ float g_vs[MTc*Dc];
__device__ float g_ka[MAc*Dc];
__device__ float g_va[MAc*Dc];
__device__ float g_kt[MSc*Dc];
__device__ float g_vt[MSc*Dc];
__device__ float g_ada[Bc*6*Dc];
__device__ float g_sc[Bc*Dc];

__device__ __nv_bfloat16 g_h_hi[MTc*Dc],  g_h_lo[MTc*Dc];
__device__ __nv_bfloat16 g_o_hi[MTc*Dc],  g_o_lo[MTc*Dc];
__device__ __nv_bfloat16 g_ff_hi[MTc*DFFc], g_ff_lo[MTc*DFFc];
__device__ __nv_bfloat16 g_adp_hi[MAc*Dc], g_adp_lo[MAc*Dc];
__device__ __nv_bfloat16 g_tsk_hi[MSc*Dc], g_tsk_lo[MSc*Dc];
__device__ __nv_bfloat16 g_w_hi[Lc*WPLc], g_w_lo[Lc*WPLc];

// ---------------- PTX helpers (arch-neutral: mma.sync + cp.async) ----------------
__device__ __forceinline__ uint32_t smem_u32(const void* p) {
    uint32_t a;
    asm("{ .reg .u64 t; cvta.to.shared.u64 t, %1; cvt.u32.u64 %0, t; }" : "=r"(a) : "l"(p));
    return a;
}

__device__ __forceinline__ void mma_bf16(float* c, const uint32_t* a, const uint32_t* b) {
    asm volatile(
        "mma.sync.aligned.m16n8k16.row.col.f32.bf16.bf16.f32 "
        "{%0,%1,%2,%3}, {%4,%5,%6,%7}, {%8,%9}, {%0,%1,%2,%3};"
        : "+f"(c[0]), "+f"(c[1]), "+f"(c[2]), "+f"(c[3])
        : "r"(a[0]), "r"(a[1]), "r"(a[2]), "r"(a[3]), "r"(b[0]), "r"(b[1]));
}

__device__ __forceinline__ void cpa16(uint32_t d, const void* s) {
    asm volatile("cp.async.cg.shared.global [%0], [%1], 16;" :: "r"(d), "l"(s));
}
#define CP_COMMIT() asm volatile("cp.async.commit_group;" ::: "memory")

__device__ __forceinline__ float gelu_t(float c) {
    float t = 0.7978845608028654f * (c + 0.044715f * c * c * c);
    return 0.5f * c * (1.f + tanhf(t));
}

// ---------------- bf16 3-pass warp-MMA GEMM ----------------
// D[M,N] = A[M,K] @ Wt[N,K]^T, fp32 accum; A=Ahi+Alo, B=Bhi+Blo; 3 passes.
// Block tile 128x128, 8 warps (2m x 4n), warp tile 64x32, K-tile 32.
// Smem per stage: Ahi|Alo|Bhi|Blo, each 128 rows x 80B (32 bf16 padded). 2 stages.
// EPI 0: C = acc + bias (f32)
// EPI 1: gelu(acc + bias) -> Chi/Clo bf16 split
// EPI 2: X += gmod[row/Tc, col] * (acc + bias)
#define STG   40960
#define GSMEM (2*STG)
template <int EPI>
__global__ __launch_bounds__(256) void mma_gemm(
    const __nv_bfloat16* __restrict__ Ahi, const __nv_bfloat16* __restrict__ Alo,
    const __nv_bfloat16* __restrict__ Bhi, const __nv_bfloat16* __restrict__ Blo,
    const float* __restrict__ bias, float* __restrict__ C,
    int M, int N, int K,
    const float* __restrict__ gmod, int gstride, float* __restrict__ X,
    __nv_bfloat16* __restrict__ Chi, __nv_bfloat16* __restrict__ Clo)
{
    extern __shared__ __align__(16) char smem[];
    const int tid  = threadIdx.x;
    const int row0 = blockIdx.y * 128;
    const int col0 = blockIdx.x * 128;
    const uint32_t sb = smem_u32(smem);

    const int w = tid >> 5, lane = tid & 31;
    const int wm = w >> 2, wn = w & 3;      // 2 x 4 warp grid
    const int g = lane >> 2, t = lane & 3;

    float acc[4][4][4];
    #pragma unroll
    for (int i = 0; i < 4; i++)
        #pragma unroll
        for (int j = 0; j < 4; j++)
            #pragma unroll
            for (int e = 0; e < 4; e++) acc[i][j][e] = 0.f;

    const int r_ld = tid >> 2;   // 0..63
    const int c_ld = tid & 3;    // 0..3 (16B chunk within 64B row)
    const int nch  = K >> 5;

    auto load_stage = [&](int st, int k0) {
        uint32_t d0 = sb + st * STG;
        #pragma unroll
        for (int q = 0; q < 2; q++) {
            int r = r_ld + q * 64;
            uint32_t dof = (uint32_t)(r * 80 + c_ld * 16);
            size_t ga = (size_t)(row0 + r) * K + k0 + c_ld * 8;
            size_t gb = (size_t)(col0 + r) * K + k0 + c_ld * 8;
            cpa16(d0 + dof,         Ahi + ga);
            cpa16(d0 + 10240 + dof, Alo + ga);
            cpa16(d0 + 20480 + dof, Bhi + gb);
            cpa16(d0 + 30720 + dof, Blo + gb);
        }
    };

    load_stage(0, 0);
    CP_COMMIT();

    for (int ch = 0; ch < nch; ch++) {
        if (ch + 1 < nch) {
            load_stage((ch + 1) & 1, (ch + 1) << 5);
            CP_COMMIT();
            asm volatile("cp.async.wait_group 1;" ::: "memory");
        } else {
            asm volatile("cp.async.wait_group 0;" ::: "memory");
        }
        __syncthreads();

        const char* s0p = smem + (ch & 1) * STG;
        #pragma unroll
        for (int ks = 0; ks < 2; ks++) {
            uint32_t ah[4][4], al[4][4], bh[4][2], bl[4][2];
            #pragma unroll
            for (int mt = 0; mt < 4; mt++) {
                const char* ap = s0p + (wm * 64 + mt * 16 + g) * 80 + ks * 32 + t * 4;
                ah[mt][0] = *(const uint32_t*)(ap);
                ah[mt][1] = *(const uint32_t*)(ap + 640);
                ah[mt][2] = *(const uint32_t*)(ap + 16);
                ah[mt][3] = *(const uint32_t*)(ap + 656);
                al[mt][0] = *(const uint32_t*)(ap + 10240);
                al[mt][1] = *(const uint32_t*)(ap + 10880);
                al[mt][2] = *(const uint32_t*)(ap + 10256);
                al[mt][3] = *(const uint32_t*)(ap + 10896);
            }
            #pragma unroll
            for (int nt = 0; nt < 4; nt++) {
                const char* bp = s0p + 20480 + (wn * 32 + nt * 8 + g) * 80 + ks * 32 + t * 4;
                bh[nt][0] = *(const uint32_t*)(bp);
                bh[nt][1] = *(const uint32_t*)(bp + 16);
                bl[nt][0] = *(const uint32_t*)(bp + 10240);
                bl[nt][1] = *(const uint32_t*)(bp + 10256);
            }
            #pragma unroll
            for (int mt = 0; mt < 4; mt++)
                #pragma unroll
                for (int nt = 0; nt < 4; nt++)
                    mma_bf16(acc[mt][nt], ah[mt], bh[nt]);
            #pragma unroll
            for (int mt = 0; mt < 4; mt++)
                #pragma unroll
                for (int nt = 0; nt < 4; nt++)
                    mma_bf16(acc[mt][nt], ah[mt], bl[nt]);
            #pragma unroll
            for (int mt = 0; mt < 4; mt++)
                #pragma unroll
                for (int nt = 0; nt < 4; nt++)
                    mma_bf16(acc[mt][nt], al[mt], bh[nt]);
        }
        __syncthreads();
    }

    // epilogue: acc element map: a0=(row,col) a1=(row,col+1) a2=(row+8,col) a3=(row+8,col+1)
    #pragma unroll
    for (int mt = 0; mt < 4; mt++) {
        const int row = row0 + wm * 64 + mt * 16 + g;
        #pragma unroll
        for (int nt = 0; nt < 4; nt++) {
            const int col = col0 + wn * 32 + nt * 8 + 2 * t;
            const float* a = acc[mt][nt];
            const float b0v = bias ? bias[col]     : 0.f;
            const float b1v = bias ? bias[col + 1] : 0.f;
            const float v0 = a[0] + b0v, v1 = a[1] + b1v;
            const float v2 = a[2] + b0v, v3 = a[3] + b1v;
            if (EPI == 0) {
                *(float2*)(C + (size_t)row * N + col)       = make_float2(v0, v1);
                *(float2*)(C + (size_t)(row + 8) * N + col) = make_float2(v2, v3);
            } else if (EPI == 1) {
                float g0 = gelu_t(v0), g1 = gelu_t(v1), g2 = gelu_t(v2), g3 = gelu_t(v3);
                __nv_bfloat16 h0 = __float2bfloat16(g0), h1 = __float2bfloat16(g1);
                __nv_bfloat16 h2 = __float2bfloat16(g2), h3 = __float2bfloat16(g3);
                *(__nv_bfloat162*)(Chi + (size_t)row * N + col)       = __nv_bfloat162(h0, h1);
                *(__nv_bfloat162*)(Chi + (size_t)(row + 8) * N + col) = __nv_bfloat162(h2, h3);
                *(__nv_bfloat162*)(Clo + (size_t)row * N + col) =
                    __nv_bfloat162(__float2bfloat16(g0 - __bfloat162float(h0)),
                                   __float2bfloat16(g1 - __bfloat162float(h1)));
                *(__nv_bfloat162*)(Clo + (size_t)(row + 8) * N + col) =
                    __nv_bfloat162(__float2bfloat16(g2 - __bfloat162float(h2)),
                                   __float2bfloat16(g3 - __bfloat162float(h3)));
            } else {
                const int bb = row >> 8;   // row / Tc (rows 0..127 of block share batch)
                const float* gm = gmod + (size_t)bb * gstride;
                float2 x0 = *(float2*)(X + (size_t)row * N + col);
                float2 x1 = *(float2*)(X + (size_t)(row + 8) * N + col);
                x0.x += gm[col] * v0;     x0.y += gm[col + 1] * v1;
                x1.x += gm[col] * v2;     x1.y += gm[col + 1] * v3;
                *(float2*)(X + (size_t)row * N + col)       = x0;
                *(float2*)(X + (size_t)(row + 8) * N + col) = x1;
            }
        }
    }
}

// ---------------- weight prep: transpose [K,N] f32 -> [N,K] bf16 hi/lo ----------------
__global__ void wprep(const float* __restrict__ W, __nv_bfloat16* __restrict__ Whi,
                      __nv_bfloat16* __restrict__ Wlo, int K, int N) {
    __shared__ float t[32][33];
    int k0 = blockIdx.x * 32, n0 = blockIdx.y * 32;
    int tx = threadIdx.x, ty = threadIdx.y;   // 32 x 8
    #pragma unroll
    for (int i = 0; i < 4; i++)
        t[ty + i * 8][tx] = W[(size_t)(k0 + ty + i * 8) * N + n0 + tx];
    __syncthreads();
    #pragma unroll
    for (int i = 0; i < 4; i++) {
        float v = t[tx][ty + i * 8];
        int n = n0 + ty + i * 8, k = k0 + tx;
        __nv_bfloat16 h = __float2bfloat16(v);
        Whi[(size_t)n * K + k] = h;
        Wlo[(size_t)n * K + k] = __float2bfloat16(v - __bfloat162float(h));
    }
}

__global__ void split_kernel(const float* __restrict__ s, __nv_bfloat16* __restrict__ hi,
                             __nv_bfloat16* __restrict__ lo, int n) {
    int i = blockIdx.x * blockDim.x + threadIdx.x;
    if (i < n) {
        float v = s[i];
        __nv_bfloat16 h = __float2bfloat16(v);
        hi[i] = h;
        lo[i] = __float2bfloat16(v - __bfloat162float(h));
    }
}

// ---------------- elementwise kernels ----------------
__global__ void copy_kernel(const float* __restrict__ src, float* __restrict__ dst, int n) {
    int i = blockIdx.x * blockDim.x + threadIdx.x;
    if (i < n) dst[i] = src[i];
}
__global__ void silu_kernel(const float* __restrict__ c, float* __restrict__ out, int n) {
    int i = blockIdx.x * blockDim.x + threadIdx.x;
    if (i < n) { float x = c[i]; out[i] = x / (1.f + expf(-x)); }
}

__device__ __forceinline__ float block_reduce_sum(float v, float* red) {
    int tid = threadIdx.x;
    red[tid] = v;
    __syncthreads();
    #pragma unroll
    for (int s = 128; s > 0; s >>= 1) {
        if (tid < s) red[tid] += red[tid + s];
        __syncthreads();
    }
    float r = red[0];
    __syncthreads();
    return r;
}

// h = ln(x)*(1+ada[sc]) + ada[sh]  -> bf16 hi/lo split
__global__ void ln_mod_split(const float* __restrict__ x, const float* __restrict__ ada,
                             int off_shift, int off_scale,
                             __nv_bfloat16* __restrict__ hi, __nv_bfloat16* __restrict__ lo) {
    __shared__ float red[256];
    int row = blockIdx.x;
    int b   = row / Tc;
    int tid = threadIdx.x;
    const float* xr = x + (size_t)row * Dc;
    float v[4], s = 0.f;
    #pragma unroll
    for (int i = 0; i < 4; i++) { v[i] = xr[tid + i * 256]; s += v[i]; }
    float mean = block_reduce_sum(s, red) * (1.f / (float)Dc);
    float sq = 0.f;
    #pragma unroll
    for (int i = 0; i < 4; i++) { float d = v[i] - mean; sq += d * d; }
    float var = block_reduce_sum(sq, red) * (1.f / (float)Dc);
    float rstd = rsqrtf(var + 1e-5f);
    const float* ab = ada + (size_t)b * 6 * Dc;
    #pragma unroll
    for (int i = 0; i < 4; i++) {
        int d = tid + i * 256;
        float a = (v[i] - mean) * rstd;
        float o = a * (1.f + ab[off_scale + d]) + ab[off_shift + d];
        __nv_bfloat16 h = __float2bfloat16(o);
        hi[(size_t)row * Dc + d] = h;
        lo[(size_t)row * Dc + d] = __float2bfloat16(o - __bfloat162float(h));
    }
}

// per-head RMSNorm + RoPE (+ uniform multiplier), in-place fp32
__global__ void rmsrope_kernel(float* __restrict__ t, const float* __restrict__ w,
                               int S, float cmul, const float* __restrict__ gate) {
    int warp = (blockIdx.x * blockDim.x + threadIdx.x) >> 5;
    int lane = threadIdx.x & 31;
    int row  = warp;
    int s    = (row / Hc) % S;
    float* p = t + (size_t)row * HDc;
    float x0 = p[lane], x1 = p[lane + 32];
    float ss = x0 * x0 + x1 * x1;
    #pragma unroll
    for (int o = 16; o; o >>= 1) ss += __shfl_xor_sync(0xffffffffu, ss, o);
    float inv = rsqrtf(ss * (1.f / (float)HDc) + 1e-6f);
    x0 = x0 * inv * w[lane];
    x1 = x1 * inv * w[lane + 32];
    float fr = (float)s * expf(-(float)lane * 0.28782313662425575f);
    float c  = cosf(fr), sn = sinf(fr);
    float mult = cmul;
    if (gate) mult *= 1.f / (1.f + expf(-gate[0]));
    p[lane]      = (x0 * c - x1 * sn) * mult;
    p[lane + 32] = (x1 * c + x0 * sn) * mult;
}

// ada: C[b,n] = silu(cond)[b,:] @ Wada[:,n] + bias
__global__ void small_gemm_kernel(const float* __restrict__ A, const float* __restrict__ W,
                                  const float* __restrict__ bias, float* __restrict__ C,
                                  int Nn, int Kk) {
    int n = blockIdx.x * blockDim.x + threadIdx.x;
    int b = blockIdx.y;
    if (n >= Nn) return;
    const float* a = A + (size_t)b * Kk;
    float acc = 0.f;
    #pragma unroll 4
    for (int k = 0; k < Kk; k++) acc += a[k] * W[(size_t)k * Nn + n];
    C[(size_t)b * Nn + n] = acc + (bias ? bias[n] : 0.f);
}

// ---------------- flash attention (fp32) over 3 KV segments, output bf16 split ----------------
__global__ __launch_bounds__(128) void flash_kernel(
    const float* __restrict__ q,
    const float* __restrict__ ks, const float* __restrict__ vs,
    const float* __restrict__ ka, const float* __restrict__ va,
    const float* __restrict__ kt, const float* __restrict__ vt,
    __nv_bfloat16* __restrict__ ohi, __nv_bfloat16* __restrict__ olo)
{
    __shared__ float4 Ks4[32][16];
    __shared__ float4 Vs4[32][16];
    int tid = threadIdx.x;
    int bh  = blockIdx.y;
    int b   = bh / Hc, h = bh % Hc;
    int qi  = blockIdx.x * 128 + tid;

    float qr[64], oa[64];
    const float* qp = q + (size_t)(b * Tc + qi) * Dc + h * HDc;
    #pragma unroll
    for (int j = 0; j < 16; j++) {
        float4 v4 = *(const float4*)&qp[j * 4];
        qr[4*j] = v4.x; qr[4*j+1] = v4.y; qr[4*j+2] = v4.z; qr[4*j+3] = v4.w;
    }
    #pragma unroll
    for (int d = 0; d < 64; d++) oa[d] = 0.f;
    float m = -1e30f, l = 0.f;

    const float* Kseg[3] = {ks, ka, kt};
    const float* Vseg[3] = {vs, va, vt};
    const int    Slen[3] = {Tc, SAc, STc};

    #pragma unroll
    for (int seg = 0; seg < 3; seg++) {
        const float* K = Kseg[seg];
        const float* V = Vseg[seg];
        int S = Slen[seg];
        for (int s0 = 0; s0 < S; s0 += 32) {
            __syncthreads();
            #pragma unroll
            for (int i = 0; i < 4; i++) {
                int idx = tid + i * 128;
                int r = idx >> 4, cc = idx & 15;
                size_t base = (size_t)(b * S + s0 + r) * Dc + h * HDc + cc * 4;
                Ks4[r][cc] = *(const float4*)&K[base];
                Vs4[r][cc] = *(const float4*)&V[base];
            }
            __syncthreads();
            float sc[32];
            float tmax = -1e30f;
            #pragma unroll
            for (int s = 0; s < 32; s++) {
                float d0 = 0.f, d1 = 0.f, d2 = 0.f, d3 = 0.f;
                #pragma unroll
                for (int j = 0; j < 16; j++) {
                    float4 kv = Ks4[s][j];
                    d0 = fmaf(qr[4*j],   kv.x, d0);
                    d1 = fmaf(qr[4*j+1], kv.y, d1);
                    d2 = fmaf(qr[4*j+2], kv.z, d2);
                    d3 = fmaf(qr[4*j+3], kv.w, d3);
                }
                float d = (d0 + d1) + (d2 + d3);
                sc[s] = d;
                tmax = fmaxf(tmax, d);
            }
            float mnew = fmaxf(m, tmax);
            float corr = __expf(m - mnew);
            l *= corr;
            #pragma unroll
            for (int d = 0; d < 64; d++) oa[d] *= corr;
            #pragma unroll
            for (int s = 0; s < 32; s++) {
                float p = __expf(sc[s] - mnew);
                l += p;
                #pragma unroll
                for (int j = 0; j < 16; j++) {
                    float4 vv = Vs4[s][j];
                    oa[4*j]   = fmaf(p, vv.x, oa[4*j]);
                    oa[4*j+1] = fmaf(p, vv.y, oa[4*j+1]);
                    oa[4*j+2] = fmaf(p, vv.z, oa[4*j+2]);
                    oa[4*j+3] = fmaf(p, vv.w, oa[4*j+3]);
                }
            }
            m = mnew;
        }
    }
    float invl = 1.f / l;
    size_t ob = (size_t)(b * Tc + qi) * Dc + h * HDc;
    #pragma unroll
    for (int d = 0; d < 64; d++) {
        float v = oa[d] * invl;
        __nv_bfloat16 hb = __float2bfloat16(v);
        ohi[ob + d] = hb;
        olo[ob + d] = __float2bfloat16(v - __bfloat162float(hb));
    }
}

// ---------------- final LN + tiny projection ----------------
__global__ void final_kernel(const float* __restrict__ x, const float* __restrict__ lw,
                             const float* __restrict__ lb, const float* __restrict__ Wout,
                             const float* __restrict__ bout, float* __restrict__ out) {
    __shared__ float red[256];
    int row = blockIdx.x;
    int tid = threadIdx.x;
    const float* xr = x + (size_t)row * Dc;
    float v[4], s = 0.f;
    #pragma unroll
    for (int i = 0; i < 4; i++) { v[i] = xr[tid + i * 256]; s += v[i]; }
    float mean = block_reduce_sum(s, red) * (1.f / (float)Dc);
    float sq = 0.f;
    #pragma unroll
    for (int i = 0; i < 4; i++) { float d = v[i] - mean; sq += d * d; }
    float var = block_reduce_sum(sq, red) * (1.f / (float)Dc);
    float rstd = rsqrtf(var + 1e-5f);
    float p0 = 0.f, p1 = 0.f, p2 = 0.f;
    #pragma unroll
    for (int i = 0; i < 4; i++) {
        int d = tid + i * 256;
        float y = (v[i] - mean) * rstd * lw[d] + lb[d];
        p0 = fmaf(y, Wout[d * OUTc + 0], p0);
        p1 = fmaf(y, Wout[d * OUTc + 1], p1);
        p2 = fmaf(y, Wout[d * OUTc + 2], p2);
    }
    p0 = block_reduce_sum(p0, red);
    p1 = block_reduce_sum(p1, red);
    p2 = block_reduce_sum(p2, red);
    if (tid == 0) {
        out[row * OUTc + 0] = p0 + bout[0];
        out[row * OUTc + 1] = p1 + bout[1];
        out[row * OUTc + 2] = p2 + bout[2];
    }
}

// ---------------- launch ----------------
extern "C" void kernel_launch(void* const* d_in, const int* in_sizes, int n_in,
                              void* d_out, int out_size)
{
    (void)in_sizes; (void)n_in; (void)out_size;
    const float* x    = (const float*)d_in[0];
    const float* cond = (const float*)d_in[1];
    const float* adp  = (const float*)d_in[2];
    const float* task = (const float*)d_in[3];
    const float* Wq   = (const float*)d_in[4];
    const float* bq   = (const float*)d_in[5];
    const float* Wks  = (const float*)d_in[6];
    const float* Wvs  = (const float*)d_in[7];
    const float* Wka  = (const float*)d_in[8];
    const float* Wva  = (const float*)d_in[9];
    const float* Wkt  = (const float*)d_in[10];
    const float* Wvt  = (const float*)d_in[11];
    const float* Wo   = (const float*)d_in[12];
    const float* bo   = (const float*)d_in[13];
    const float* qnw  = (const float*)d_in[14];
    const float* knw  = (const float*)d_in[15];
    const float* gate = (const float*)d_in[16];
    const float* Wada = (const float*)d_in[17];
    const float* bada = (const float*)d_in[18];
    const float* W1   = (const float*)d_in[19];
    const float* b1   = (const float*)d_in[20];
    const float* W2   = (const float*)d_in[21];
    const float* b2   = (const float*)d_in[22];
    const float* lnfw = (const float*)d_in[23];
    const float* lnfb = (const float*)d_in[24];
    const float* Wout = (const float*)d_in[25];
    const float* bout = (const float*)d_in[26];
    float* out = (float*)d_out;

    cudaFuncSetAttribute(mma_gemm<0>, cudaFuncAttributeMaxDynamicSharedMemorySize, GSMEM);
    cudaFuncSetAttribute(mma_gemm<1>, cudaFuncAttributeMaxDynamicSharedMemorySize, GSMEM);
    cudaFuncSetAttribute(mma_gemm<2>, cudaFuncAttributeMaxDynamicSharedMemorySize, GSMEM);

    float *px, *pq, *pks, *pvs, *pka, *pva, *pkt, *pvt, *pada, *psc;
    __nv_bfloat16 *phh, *phl, *poh, *pol, *pfh, *pfl, *pah, *pal, *pth, *ptl, *pwh, *pwl;
    cudaGetSymbolAddress((void**)&px,  g_x);
    cudaGetSymbolAddress((void**)&pq,  g_q);
    cudaGetSymbolAddress((void**)&pks, g_ks);
    cudaGetSymbolAddress((void**)&pvs, g_vs);
    cudaGetSymbolAddress((void**)&pka, g_ka);
    cudaGetSymbolAddress((void**)&pva, g_va);
    cudaGetSymbolAddress((void**)&pkt, g_kt);
    cudaGetSymbolAddress((void**)&pvt, g_vt);
    cudaGetSymbolAddress((void**)&pada, g_ada);
    cudaGetSymbolAddress((void**)&psc,  g_sc);
    cudaGetSymbolAddress((void**)&phh, g_h_hi);  cudaGetSymbolAddress((void**)&phl, g_h_lo);
    cudaGetSymbolAddress((void**)&poh, g_o_hi);  cudaGetSymbolAddress((void**)&pol, g_o_lo);
    cudaGetSymbolAddress((void**)&pfh, g_ff_hi); cudaGetSymbolAddress((void**)&pfl, g_ff_lo);
    cudaGetSymbolAddress((void**)&pah, g_adp_hi); cudaGetSymbolAddress((void**)&pal, g_adp_lo);
    cudaGetSymbolAddress((void**)&pth, g_tsk_hi); cudaGetSymbolAddress((void**)&ptl, g_tsk_lo);
    cudaGetSymbolAddress((void**)&pwh, g_w_hi);  cudaGetSymbolAddress((void**)&pwl, g_w_lo);

    // per-call prep: x copy, silu(cond), adp/task split, weight transpose+split
    copy_kernel<<<(MTc*Dc)/256, 256>>>(x, px, MTc*Dc);
    silu_kernel<<<(Bc*Dc)/256, 256>>>(cond, psc, Bc*Dc);
    split_kernel<<<(MAc*Dc)/256, 256>>>(adp,  pah, pal, MAc*Dc);
    split_kernel<<<(MSc*Dc)/256, 256>>>(task, pth, ptl, MSc*Dc);

    const float* wsrc[8] = {Wq, Wks, Wvs, Wka, Wva, Wkt, Wvt, Wo};
    for (int i = 0; i < Lc; i++) {
        size_t base = (size_t)i * WPLc;
        for (int mtx = 0; mtx < 8; mtx++) {
            wprep<<<dim3(Dc/32, Dc/32), dim3(32, 8)>>>(
                wsrc[mtx] + (size_t)i * DDc, pwh + base + (size_t)mtx * DDc,
                pwl + base + (size_t)mtx * DDc, Dc, Dc);
        }
        wprep<<<dim3(Dc/32, DFFc/32), dim3(32, 8)>>>(
            W1 + (size_t)i * Dc * DFFc, pwh + base + 8*DDc, pwl + base + 8*DDc, Dc, DFFc);
        wprep<<<dim3(DFFc/32, Dc/32), dim3(32, 8)>>>(
            W2 + (size_t)i * DFFc * Dc, pwh + base + 8*DDc + (size_t)Dc*DFFc,
            pwl + base + 8*DDc + (size_t)Dc*DFFc, DFFc, Dc);
    }

    for (int i = 0; i < Lc; i++) {
        size_t wb = (size_t)i * WPLc;
        __nv_bfloat16* wq  = pwh + wb + 0*(size_t)DDc; __nv_bfloat16* wql = pwl + wb + 0*(size_t)DDc;
        __nv_bfloat16* wks = pwh + wb + 1*(size_t)DDc; __nv_bfloat16* wksl= pwl + wb + 1*(size_t)DDc;
        __nv_bfloat16* wvs = pwh + wb + 2*(size_t)DDc; __nv_bfloat16* wvsl= pwl + wb + 2*(size_t)DDc;
        __nv_bfloat16* wka = pwh + wb + 3*(size_t)DDc; __nv_bfloat16* wkal= pwl + wb + 3*(size_t)DDc;
        __nv_bfloat16* wva = pwh + wb + 4*(size_t)DDc; __nv_bfloat16* wval= pwl + wb + 4*(size_t)DDc;
        __nv_bfloat16* wkt = pwh + wb + 5*(size_t)DDc; __nv_bfloat16* wktl= pwl + wb + 5*(size_t)DDc;
        __nv_bfloat16* wvt = pwh + wb + 6*(size_t)DDc; __nv_bfloat16* wvtl= pwl + wb + 6*(size_t)DDc;
        __nv_bfloat16* wo  = pwh + wb + 7*(size_t)DDc; __nv_bfloat16* wol = pwl + wb + 7*(size_t)DDc;
        __nv_bfloat16* w1  = pwh + wb + 8*(size_t)DDc; __nv_bfloat16* w1l = pwl + wb + 8*(size_t)DDc;
        __nv_bfloat16* w2  = pwh + wb + 8*(size_t)DDc + (size_t)Dc*DFFc;
        __nv_bfloat16* w2l = pwl + wb + 8*(size_t)DDc + (size_t)Dc*DFFc;

        small_gemm_kernel<<<dim3((6*Dc)/256, Bc), 256>>>(
            psc, Wada + (size_t)i*Dc*6*Dc, bada + (size_t)i*6*Dc, pada, 6*Dc, Dc);

        ln_mod_split<<<MTc, 256>>>(px, pada, 0, Dc, phh, phl);

        mma_gemm<0><<<dim3(Dc/128, MTc/128), 256, GSMEM>>>(phh, phl, wq,  wql,  bq + (size_t)i*Dc, pq,  MTc, Dc, Dc, nullptr, 0, nullptr, nullptr, nullptr);
        mma_gemm<0><<<dim3(Dc/128, MTc/128), 256, GSMEM>>>(phh, phl, wks, wksl, nullptr,           pks, MTc, Dc, Dc, nullptr, 0, nullptr, nullptr, nullptr);
        mma_gemm<0><<<dim3(Dc/128, MTc/128), 256, GSMEM>>>(phh, phl, wvs, wvsl, nullptr,           pvs, MTc, Dc, Dc, nullptr, 0, nullptr, nullptr, nullptr);
        mma_gemm<0><<<dim3(Dc/128, MAc/128), 256, GSMEM>>>(pah, pal, wka, wkal, nullptr,           pka, MAc, Dc, Dc, nullptr, 0, nullptr, nullptr, nullptr);
        mma_gemm<0><<<dim3(Dc/128, MAc/128), 256, GSMEM>>>(pah, pal, wva, wval, nullptr,           pva, MAc, Dc, Dc, nullptr, 0, nullptr, nullptr, nullptr);
        mma_gemm<0><<<dim3(Dc/128, MSc/128), 256, GSMEM>>>(pth, ptl, wkt, wktl, nullptr,           pkt, MSc, Dc, Dc, nullptr, 0, nullptr, nullptr, nullptr);
        mma_gemm<0><<<dim3(Dc/128, MSc/128), 256, GSMEM>>>(pth, ptl, wvt, wvtl, nullptr,           pvt, MSc, Dc, Dc, nullptr, 0, nullptr, nullptr, nullptr);

        rmsrope_kernel<<<(MTc*Hc*32)/256, 256>>>(pq,  qnw + (size_t)i*HDc, Tc,  0.125f, nullptr);
        rmsrope_kernel<<<(MTc*Hc*32)/256, 256>>>(pks, knw + (size_t)i*HDc, Tc,  1.f,    nullptr);
        rmsrope_kernel<<<(MAc*Hc*32)/256, 256>>>(pka, knw + (size_t)i*HDc, SAc, 1.f,    nullptr);
        rmsrope_kernel<<<(MSc*Hc*32)/256, 256>>>(pkt, knw + (size_t)i*HDc, STc, 1.f,    gate + i);

        flash_kernel<<<dim3(Tc/128, Bc*Hc), 128>>>(pq, pks, pvs, pka, pva, pkt, pvt, poh, pol);

        mma_gemm<2><<<dim3(Dc/128, MTc/128), 256, GSMEM>>>(poh, pol, wo, wol, bo + (size_t)i*Dc, nullptr,
                                                           MTc, Dc, Dc, pada + 2*Dc, 6*Dc, px, nullptr, nullptr);

        ln_mod_split<<<MTc, 256>>>(px, pada, 3*Dc, 4*Dc, phh, phl);

        mma_gemm<1><<<dim3(DFFc/128, MTc/128), 256, GSMEM>>>(phh, phl, w1, w1l, b1 + (size_t)i*DFFc, nullptr,
                                                             MTc, DFFc, Dc, nullptr, 0, nullptr, pfh, pfl);

        mma_gemm<2><<<dim3(Dc/128, MTc/128), 256, GSMEM>>>(pfh, pfl, w2, w2l, b2 + (size_t)i*Dc, nullptr,
                                                           MTc, Dc, DFFc, pada + 5*Dc, 6*Dc, px, nullptr, nullptr);
    }

    final_kernel<<<MTc, 256>>>(px, lnfw, lnfb, Wout, bout, out);
}

// round 6
// speedup vs baseline: 1.2118x; 1.2118x over previous
#include <cuda_runtime.h>
#include <cuda_bf16.h>
#include <math.h>
#include <stdint.h>

#define Lc 6
#define Bc 32
#define Tc 256
#define SAc 512
#define STc 128
#define Dc 1024
#define Hc 16
#define HDc 64
#define DFFc 4096
#define OUTc 3
#define MTc (Bc*Tc)
#define MAc (Bc*SAc)
#define MSc (Bc*STc)
#define DDc (Dc*Dc)
#define WPLc (8*DDc + Dc*DFFc + DFFc*Dc)

__device__ float g_x[MTc*Dc];
__device__ float g_q[MTc*Dc];
__device__ float g_ks[MTc*Dc];
__device__ float g_vs[MTc*Dc];
__device__ float g_ka[MAc*Dc];
__device__ float g_va[MAc*Dc];
__device__ float g_kt[MSc*Dc];
__device__ float g_vt[MSc*Dc];
__device__ float g_ada[Bc*6*Dc];
__device__ float g_sc[Bc*Dc];

__device__ __align__(256) __nv_bfloat16 g_h_hi[MTc*Dc],  g_h_lo[MTc*Dc];
__device__ __align__(256) __nv_bfloat16 g_o_hi[MTc*Dc],  g_o_lo[MTc*Dc];
__device__ __align__(256) __nv_bfloat16 g_ff_hi[MTc*DFFc], g_ff_lo[MTc*DFFc];
__device__ __align__(256) __nv_bfloat16 g_adp_hi[MAc*Dc], g_adp_lo[MAc*Dc];
__device__ __align__(256) __nv_bfloat16 g_tsk_hi[MSc*Dc], g_tsk_lo[MSc*Dc];
__device__ __align__(256) __nv_bfloat16 g_w_hi[Lc*WPLc], g_w_lo[Lc*WPLc];

__device__ __forceinline__ uint32_t smem_u32(const void* p) {
    uint32_t a;
    asm("{ .reg .u64 t; cvta.to.shared.u64 t, %1; cvt.u32.u64 %0, t; }" : "=r"(a) : "l"(p));
    return a;
}
#define MBAR_INIT(a, n) asm volatile("mbarrier.init.shared.b64 [%0], %1;" :: "r"(a), "r"(n) : "memory")
#define MBAR_EXPECT(a, tx) asm volatile("mbarrier.arrive.expect_tx.shared.b64 _, [%0], %1;" :: "r"(a), "r"(tx) : "memory")
#define MBAR_WAIT(a, ph) do { \
    uint32_t _m = (a), _p = (ph), _d; \
    asm volatile("{ .reg .pred p; mbarrier.try_wait.parity.acquire.cta.shared::cta.b64 p, [%1], %2; selp.b32 %0,1,0,p; }" \
        : "=r"(_d) : "r"(_m), "r"(_p) : "memory"); \
    if (!_d) { \
        asm volatile("{ .reg .pred P1; WL_%=: mbarrier.try_wait.parity.acquire.cta.shared::cta.b64 P1, [%0], %1, 0x989680; @P1 bra.uni WD_%=; bra.uni WL_%=; WD_%=: }" \
            :: "r"(_m), "r"(_p) : "memory"); \
    } } while (0)
#define BULK8K(dst, src, bar) asm volatile( \
    "cp.async.bulk.shared::cluster.global.mbarrier::complete_tx::bytes [%0], [%1], 8192, [%2];" \
    :: "r"(dst), "l"(src), "r"(bar) : "memory")
#define FENCE_ASYNC() asm volatile("fence.proxy.async.shared::cta;" ::: "memory")
#define LDSM4(r, a) asm volatile( \
    "ldmatrix.sync.aligned.m8n8.x4.shared.b16 {%0,%1,%2,%3}, [%4];" \
    : "=r"((r)[0]), "=r"((r)[1]), "=r"((r)[2]), "=r"((r)[3]) : "r"(a))

__device__ __forceinline__ void mma_bf16(float* c, const uint32_t* a, const uint32_t* b) {
    asm volatile(
        "mma.sync.aligned.m16n8k16.row.col.f32.bf16.bf16.f32 "
        "{%0,%1,%2,%3}, {%4,%5,%6,%7}, {%8,%9}, {%0,%1,%2,%3};"
        : "+f"(c[0]), "+f"(c[1]), "+f"(c[2]), "+f"(c[3])
        : "r"(a[0]), "r"(a[1]), "r"(a[2]), "r"(a[3]), "r"(b[0]), "r"(b[1]));
}
__device__ __forceinline__ float gelu_t(float c) {
    float t = 0.7978845608028654f * (c + 0.044715f * c * c * c);
    return 0.5f * c * (1.f + tanhf(t));
}
// (row,col) of [M,Ncols] -> tile-major swizzled offset (128x32 tiles, 8KB)
__device__ __forceinline__ size_t tile_off(int row, int col, int Ncols) {
    int r = row & 127;
    int cp = ((col >> 3) & 3) ^ ((r >> 1) & 3);
    return ((size_t)(row >> 7) * (Ncols >> 5) + (col >> 5)) * 4096 + r * 32 + cp * 8 + (col & 7);
}

// ---- bf16 3-pass MMA GEMM, bulk-copy 4-stage pipeline ----
// EPI 0: C=acc+bias f32 | EPI 1: gelu->tile-major hi/lo | EPI 2: X += gmod*(acc+bias)
#define GSMEM (131072 + 64)
template <int EPI>
__global__ __launch_bounds__(256) void mma_gemm(
    const __nv_bfloat16* __restrict__ Ahi, const __nv_bfloat16* __restrict__ Alo,
    const __nv_bfloat16* __restrict__ Bhi, const __nv_bfloat16* __restrict__ Blo,
    const float* __restrict__ bias, float* __restrict__ C, int M, int N, int K,
    const float* __restrict__ gmod, int gstride, float* __restrict__ X,
    __nv_bfloat16* __restrict__ Chi, __nv_bfloat16* __restrict__ Clo)
{
    extern __shared__ __align__(128) char smem[];
    const int tid = threadIdx.x;
    const uint32_t sb = smem_u32(smem);
    const uint32_t mb = sb + 131072;
    const int Kt = K >> 5;
    const size_t abase = (size_t)blockIdx.y * Kt * 4096;
    const size_t bbase = (size_t)blockIdx.x * Kt * 4096;

    if (tid == 0) {
        for (int s = 0; s < 4; s++) MBAR_INIT(mb + 8 * s, 1);
        FENCE_ASYNC();
    }
    __syncthreads();

    auto issue = [&](int slot, int c) {
        uint32_t d = sb + slot * 32768;
        uint32_t bar = mb + 8 * slot;
        MBAR_EXPECT(bar, 32768u);
        BULK8K(d,         Ahi + abase + (size_t)c * 4096, bar);
        BULK8K(d + 8192,  Alo + abase + (size_t)c * 4096, bar);
        BULK8K(d + 16384, Bhi + bbase + (size_t)c * 4096, bar);
        BULK8K(d + 24576, Blo + bbase + (size_t)c * 4096, bar);
    };
    if (tid == 0)
        for (int s = 0; s < 4; s++) issue(s, s);

    const int w = tid >> 5, lane = tid & 31;
    const int wm = w >> 2, wn = w & 3;
    const int g = lane >> 2, t = lane & 3;

    const int ra  = (lane & 7) + ((lane >> 3) & 1) * 8;
    const int sa  = lane >> 4;
    const int s3a = (ra >> 1) & 3;
    const int rb  = (lane & 7) + (lane >> 4) * 8;
    const int sbk = (lane >> 3) & 1;
    const int s3b = (rb >> 1) & 3;

    uint32_t aoff[2][4], boff[2][2];
    #pragma unroll
    for (int ks = 0; ks < 2; ks++) {
        #pragma unroll
        for (int mt = 0; mt < 4; mt++)
            aoff[ks][mt] = (uint32_t)((wm * 64 + mt * 16 + ra) * 64 + (((ks * 2 + sa) ^ s3a) * 16));
        #pragma unroll
        for (int np = 0; np < 2; np++)
            boff[ks][np] = (uint32_t)((wn * 32 + np * 16 + rb) * 64 + (((ks * 2 + sbk) ^ s3b) * 16));
    }

    float acc[4][4][4];
    #pragma unroll
    for (int i = 0; i < 4; i++)
        #pragma unroll
        for (int j = 0; j < 4; j++)
            #pragma unroll
            for (int e = 0; e < 4; e++) acc[i][j][e] = 0.f;

    for (int c = 0; c < Kt; c++) {
        const int slot = c & 3;
        MBAR_WAIT(mb + 8 * slot, (c >> 2) & 1);
        const uint32_t base = sb + slot * 32768;
        #pragma unroll
        for (int ks = 0; ks < 2; ks++) {
            uint32_t ah[4][4], al[4][4], bh[2][4], bl[2][4];
            #pragma unroll
            for (int mt = 0; mt < 4; mt++) {
                LDSM4(ah[mt], base + aoff[ks][mt]);
                LDSM4(al[mt], base + 8192 + aoff[ks][mt]);
            }
            #pragma unroll
            for (int np = 0; np < 2; np++) {
                LDSM4(bh[np], base + 16384 + boff[ks][np]);
                LDSM4(bl[np], base + 24576 + boff[ks][np]);
            }
            #pragma unroll
            for (int mt = 0; mt < 4; mt++)
                #pragma unroll
                for (int nt = 0; nt < 4; nt++)
                    mma_bf16(acc[mt][nt], ah[mt], &bh[nt >> 1][(nt & 1) * 2]);
            #pragma unroll
            for (int mt = 0; mt < 4; mt++)
                #pragma unroll
                for (int nt = 0; nt < 4; nt++)
                    mma_bf16(acc[mt][nt], ah[mt], &bl[nt >> 1][(nt & 1) * 2]);
            #pragma unroll
            for (int mt = 0; mt < 4; mt++)
                #pragma unroll
                for (int nt = 0; nt < 4; nt++)
                    mma_bf16(acc[mt][nt], al[mt], &bh[nt >> 1][(nt & 1) * 2]);
        }
        __syncthreads();
        if (tid == 0 && c + 4 < Kt) { FENCE_ASYNC(); issue(slot, c + 4); }
    }

    const int row0 = blockIdx.y * 128, col0 = blockIdx.x * 128;
    #pragma unroll
    for (int mt = 0; mt < 4; mt++) {
        const int row = row0 + wm * 64 + mt * 16 + g;
        #pragma unroll
        for (int nt = 0; nt < 4; nt++) {
            const int col = col0 + wn * 32 + nt * 8 + 2 * t;
            const float* a = acc[mt][nt];
            const float b0v = bias ? bias[col] : 0.f;
            const float b1v = bias ? bias[col + 1] : 0.f;
            const float v0 = a[0] + b0v, v1 = a[1] + b1v;
            const float v2 = a[2] + b0v, v3 = a[3] + b1v;
            if (EPI == 0) {
                *(float2*)(C + (size_t)row * N + col)       = make_float2(v0, v1);
                *(float2*)(C + (size_t)(row + 8) * N + col) = make_float2(v2, v3);
            } else if (EPI == 1) {
                float g0 = gelu_t(v0), g1 = gelu_t(v1), g2 = gelu_t(v2), g3 = gelu_t(v3);
                __nv_bfloat16 h0 = __float2bfloat16(g0), h1 = __float2bfloat16(g1);
                __nv_bfloat16 h2 = __float2bfloat16(g2), h3 = __float2bfloat16(g3);
                size_t o0 = tile_off(row, col, N), o1 = tile_off(row + 8, col, N);
                *(__nv_bfloat162*)(Chi + o0) = __nv_bfloat162(h0, h1);
                *(__nv_bfloat162*)(Chi + o1) = __nv_bfloat162(h2, h3);
                *(__nv_bfloat162*)(Clo + o0) =
                    __nv_bfloat162(__float2bfloat16(g0 - __bfloat162float(h0)),
                                   __float2bfloat16(g1 - __bfloat162float(h1)));
                *(__nv_bfloat162*)(Clo + o1) =
                    __nv_bfloat162(__float2bfloat16(g2 - __bfloat162float(h2)),
                                   __float2bfloat16(g3 - __bfloat162float(h3)));
            } else {
                const int bb = row >> 8;
                const float* gm = gmod + (size_t)bb * gstride;
                float2 x0 = *(float2*)(X + (size_t)row * N + col);
                float2 x1 = *(float2*)(X + (size_t)(row + 8) * N + col);
                x0.x += gm[col] * v0;  x0.y += gm[col + 1] * v1;
                x1.x += gm[col] * v2;  x1.y += gm[col + 1] * v3;
                *(float2*)(X + (size_t)row * N + col)       = x0;
                *(float2*)(X + (size_t)(row + 8) * N + col) = x1;
            }
        }
    }
}

// W[K,N] f32 -> tile-major swizzled bf16 hi/lo of Wt[N,K]
__global__ __launch_bounds__(256) void wprep(const float* __restrict__ W,
    __nv_bfloat16* __restrict__ Whi, __nv_bfloat16* __restrict__ Wlo, int K, int N) {
    __shared__ float s[32 * 128];
    const int i = blockIdx.x, j = blockIdx.y;
    #pragma unroll
    for (int e = 0; e < 16; e++) {
        int idx = threadIdx.x + e * 256;
        int kk = idx >> 7, r = idx & 127;
        s[kk * 128 + r] = W[(size_t)(j * 32 + kk) * N + i * 128 + r];
    }
    __syncthreads();
    const size_t tbase = ((size_t)i * (K >> 5) + j) * 4096;
    #pragma unroll
    for (int e = 0; e < 2; e++) {
        int q = threadIdx.x * 2 + e;
        int r = q >> 2, cp = q & 3;
        int c = cp ^ ((r >> 1) & 3);
        uint32_t hw[4], lw[4];
        #pragma unroll
        for (int u = 0; u < 4; u++) {
            float v0 = s[(c * 8 + 2 * u) * 128 + r];
            float v1 = s[(c * 8 + 2 * u + 1) * 128 + r];
            __nv_bfloat16 h0 = __float2bfloat16(v0), h1 = __float2bfloat16(v1);
            __nv_bfloat162 hp(h0, h1);
            __nv_bfloat162 lp(__float2bfloat16(v0 - __bfloat162float(h0)),
                              __float2bfloat16(v1 - __bfloat162float(h1)));
            hw[u] = *(uint32_t*)&hp;
            lw[u] = *(uint32_t*)&lp;
        }
        *(uint4*)(Whi + tbase + r * 32 + cp * 8) = make_uint4(hw[0], hw[1], hw[2], hw[3]);
        *(uint4*)(Wlo + tbase + r * 32 + cp * 8) = make_uint4(lw[0], lw[1], lw[2], lw[3]);
    }
}

// fp32 [M,1024] row-major -> tile-major swizzled hi/lo
__global__ void split_tile(const float* __restrict__ s, __nv_bfloat16* __restrict__ hi,
                           __nv_bfloat16* __restrict__ lo) {
    int idx = blockIdx.x * 256 + threadIdx.x;
    int row = idx >> 10, d = idx & 1023;
    float v = s[idx];
    __nv_bfloat16 h = __float2bfloat16(v);
    size_t o = tile_off(row, d, Dc);
    hi[o] = h;
    lo[o] = __float2bfloat16(v - __bfloat162float(h));
}

__global__ void copy_kernel(const float* __restrict__ src, float* __restrict__ dst, int n) {
    int i = blockIdx.x * blockDim.x + threadIdx.x;
    if (i < n) dst[i] = src[i];
}
__global__ void silu_kernel(const float* __restrict__ c, float* __restrict__ out, int n) {
    int i = blockIdx.x * blockDim.x + threadIdx.x;
    if (i < n) { float x = c[i]; out[i] = x / (1.f + expf(-x)); }
}
__device__ __forceinline__ float block_reduce_sum(float v, float* red) {
    int tid = threadIdx.x;
    red[tid] = v;
    __syncthreads();
    #pragma unroll
    for (int s = 128; s > 0; s >>= 1) {
        if (tid < s) red[tid] += red[tid + s];
        __syncthreads();
    }
    float r = red[0];
    __syncthreads();
    return r;
}

__global__ void ln_mod_split(const float* __restrict__ x, const float* __restrict__ ada,
                             int off_shift, int off_scale,
                             __nv_bfloat16* __restrict__ hi, __nv_bfloat16* __restrict__ lo) {
    __shared__ float red[256];
    int row = blockIdx.x, b = row / Tc, tid = threadIdx.x;
    const float* xr = x + (size_t)row * Dc;
    float v[4], s = 0.f;
    #pragma unroll
    for (int i = 0; i < 4; i++) { v[i] = xr[tid + i * 256]; s += v[i]; }
    float mean = block_reduce_sum(s, red) * (1.f / 1024.f);
    float sq = 0.f;
    #pragma unroll
    for (int i = 0; i < 4; i++) { float d = v[i] - mean; sq += d * d; }
    float rstd = rsqrtf(block_reduce_sum(sq, red) * (1.f / 1024.f) + 1e-5f);
    const float* ab = ada + (size_t)b * 6 * Dc;
    #pragma unroll
    for (int i = 0; i < 4; i++) {
        int d = tid + i * 256;
        float o = (v[i] - mean) * rstd * (1.f + ab[off_scale + d]) + ab[off_shift + d];
        __nv_bfloat16 h = __float2bfloat16(o);
        size_t off = tile_off(row, d, Dc);
        hi[off] = h;
        lo[off] = __float2bfloat16(o - __bfloat162float(h));
    }
}

__global__ void rmsrope_kernel(float* __restrict__ t, const float* __restrict__ w,
                               int S, float cmul, const float* __restrict__ gate) {
    int warp = (blockIdx.x * blockDim.x + threadIdx.x) >> 5;
    int lane = threadIdx.x & 31;
    int s = (warp / Hc) % S;
    float* p = t + (size_t)warp * HDc;
    float x0 = p[lane], x1 = p[lane + 32];
    float ss = x0 * x0 + x1 * x1;
    #pragma unroll
    for (int o = 16; o; o >>= 1) ss += __shfl_xor_sync(0xffffffffu, ss, o);
    float inv = rsqrtf(ss * (1.f / 64.f) + 1e-6f);
    x0 = x0 * inv * w[lane];
    x1 = x1 * inv * w[lane + 32];
    float fr = (float)s * expf(-(float)lane * 0.28782313662425575f);
    float c = cosf(fr), sn = sinf(fr);
    float mult = cmul;
    if (gate) mult *= 1.f / (1.f + expf(-gate[0]));
    p[lane]      = (x0 * c - x1 * sn) * mult;
    p[lane + 32] = (x1 * c + x0 * sn) * mult;
}

__global__ void small_gemm_kernel(const float* __restrict__ A, const float* __restrict__ W,
                                  const float* __restrict__ bias, float* __restrict__ C,
                                  int Nn, int Kk) {
    int n = blockIdx.x * blockDim.x + threadIdx.x;
    int b = blockIdx.y;
    if (n >= Nn) return;
    const float* a = A + (size_t)b * Kk;
    float acc = 0.f;
    #pragma unroll 4
    for (int k = 0; k < Kk; k++) acc += a[k] * W[(size_t)k * Nn + n];
    C[(size_t)b * Nn + n] = acc + (bias ? bias[n] : 0.f);
}

// flash attention fp32, output tile-major bf16 hi/lo
__global__ __launch_bounds__(128) void flash_kernel(
    const float* __restrict__ q,
    const float* __restrict__ ks, const float* __restrict__ vs,
    const float* __restrict__ ka, const float* __restrict__ va,
    const float* __restrict__ kt, const float* __restrict__ vt,
    __nv_bfloat16* __restrict__ ohi, __nv_bfloat16* __restrict__ olo)
{
    __shared__ float4 Ks4[32][16];
    __shared__ float4 Vs4[32][16];
    int tid = threadIdx.x, bh = blockIdx.y;
    int b = bh / Hc, h = bh % Hc;
    int qi = blockIdx.x * 128 + tid;

    float qr[64], oa[64];
    const float* qp = q + (size_t)(b * Tc + qi) * Dc + h * HDc;
    #pragma unroll
    for (int j = 0; j < 16; j++) {
        float4 v4 = *(const float4*)&qp[j * 4];
        qr[4*j] = v4.x; qr[4*j+1] = v4.y; qr[4*j+2] = v4.z; qr[4*j+3] = v4.w;
    }
    #pragma unroll
    for (int d = 0; d < 64; d++) oa[d] = 0.f;
    float m = -1e30f, l = 0.f;

    const float* Kseg[3] = {ks, ka, kt};
    const float* Vseg[3] = {vs, va, vt};
    const int Slen[3] = {Tc, SAc, STc};

    #pragma unroll
    for (int seg = 0; seg < 3; seg++) {
        const float* K = Kseg[seg];
        const float* V = Vseg[seg];
        int S = Slen[seg];
        for (int s0 = 0; s0 < S; s0 += 32) {
            __syncthreads();
            #pragma unroll
            for (int i = 0; i < 4; i++) {
                int idx = tid + i * 128;
                int r = idx >> 4, cc = idx & 15;
                size_t base = (size_t)(b * S + s0 + r) * Dc + h * HDc + cc * 4;
                Ks4[r][cc] = *(const float4*)&K[base];
                Vs4[r][cc] = *(const float4*)&V[base];
            }
            __syncthreads();
            float sc[32], tmax = -1e30f;
            #pragma unroll
            for (int s = 0; s < 32; s++) {
                float d0 = 0.f, d1 = 0.f, d2 = 0.f, d3 = 0.f;
                #pragma unroll
                for (int j = 0; j < 16; j++) {
                    float4 kv = Ks4[s][j];
                    d0 = fmaf(qr[4*j],   kv.x, d0);
                    d1 = fmaf(qr[4*j+1], kv.y, d1);
                    d2 = fmaf(qr[4*j+2], kv.z, d2);
                    d3 = fmaf(qr[4*j+3], kv.w, d3);
                }
                sc[s] = (d0 + d1) + (d2 + d3);
                tmax = fmaxf(tmax, sc[s]);
            }
            float mnew = fmaxf(m, tmax);
            float corr = __expf(m - mnew);
            l *= corr;
            #pragma unroll
            for (int d = 0; d < 64; d++) oa[d] *= corr;
            #pragma unroll
            for (int s = 0; s < 32; s++) {
                float p = __expf(sc[s] - mnew);
                l += p;
                #pragma unroll
                for (int j = 0; j < 16; j++) {
                    float4 vv = Vs4[s][j];
                    oa[4*j]   = fmaf(p, vv.x, oa[4*j]);
                    oa[4*j+1] = fmaf(p, vv.y, oa[4*j+1]);
                    oa[4*j+2] = fmaf(p, vv.z, oa[4*j+2]);
                    oa[4*j+3] = fmaf(p, vv.w, oa[4*j+3]);
                }
            }
            m = mnew;
        }
    }
    float invl = 1.f / l;
    int orow = b * Tc + qi;
    #pragma unroll
    for (int d = 0; d < 64; d++) {
        float v = oa[d] * invl;
        __nv_bfloat16 hb = __float2bfloat16(v);
        size_t o = tile_off(orow, h * HDc + d, Dc);
        ohi[o] = hb;
        olo[o] = __float2bfloat16(v - __bfloat162float(hb));
    }
}

__global__ void final_kernel(const float* __restrict__ x, const float* __restrict__ lw,
                             const float* __restrict__ lb, const float* __restrict__ Wout,
                             const float* __restrict__ bout, float* __restrict__ out) {
    __shared__ float red[256];
    int row = blockIdx.x, tid = threadIdx.x;
    const float* xr = x + (size_t)row * Dc;
    float v[4], s = 0.f;
    #pragma unroll
    for (int i = 0; i < 4; i++) { v[i] = xr[tid + i * 256]; s += v[i]; }
    float mean = block_reduce_sum(s, red) * (1.f / 1024.f);
    float sq = 0.f;
    #pragma unroll
    for (int i = 0; i < 4; i++) { float d = v[i] - mean; sq += d * d; }
    float rstd = rsqrtf(block_reduce_sum(sq, red) * (1.f / 1024.f) + 1e-5f);
    float p0 = 0.f, p1 = 0.f, p2 = 0.f;
    #pragma unroll
    for (int i = 0; i < 4; i++) {
        int d = tid + i * 256;
        float y = (v[i] - mean) * rstd * lw[d] + lb[d];
        p0 = fmaf(y, Wout[d * OUTc + 0], p0);
        p1 = fmaf(y, Wout[d * OUTc + 1], p1);
        p2 = fmaf(y, Wout[d * OUTc + 2], p2);
    }
    p0 = block_reduce_sum(p0, red);
    p1 = block_reduce_sum(p1, red);
    p2 = block_reduce_sum(p2, red);
    if (tid == 0) {
        out[row * OUTc + 0] = p0 + bout[0];
        out[row * OUTc + 1] = p1 + bout[1];
        out[row * OUTc + 2] = p2 + bout[2];
    }
}

extern "C" void kernel_launch(void* const* d_in, const int* in_sizes, int n_in,
                              void* d_out, int out_size)
{
    (void)in_sizes; (void)n_in; (void)out_size;
    const float* x    = (const float*)d_in[0];
    const float* cond = (const float*)d_in[1];
    const float* adp  = (const float*)d_in[2];
    const float* task = (const float*)d_in[3];
    const float* Wq   = (const float*)d_in[4];
    const float* bq   = (const float*)d_in[5];
    const float* Wks  = (const float*)d_in[6];
    const float* Wvs  = (const float*)d_in[7];
    const float* Wka  = (const float*)d_in[8];
    const float* Wva  = (const float*)d_in[9];
    const float* Wkt  = (const float*)d_in[10];
    const float* Wvt  = (const float*)d_in[11];
    const float* Wo   = (const float*)d_in[12];
    const float* bo   = (const float*)d_in[13];
    const float* qnw  = (const float*)d_in[14];
    const float* knw  = (const float*)d_in[15];
    const float* gate = (const float*)d_in[16];
    const float* Wada = (const float*)d_in[17];
    const float* bada = (const float*)d_in[18];
    const float* W1   = (const float*)d_in[19];
    const float* b1   = (const float*)d_in[20];
    const float* W2   = (const float*)d_in[21];
    const float* b2   = (const float*)d_in[22];
    const float* lnfw = (const float*)d_in[23];
    const float* lnfb = (const float*)d_in[24];
    const float* Wout = (const float*)d_in[25];
    const float* bout = (const float*)d_in[26];
    float* out = (float*)d_out;

    cudaFuncSetAttribute(mma_gemm<0>, cudaFuncAttributeMaxDynamicSharedMemorySize, GSMEM);
    cudaFuncSetAttribute(mma_gemm<1>, cudaFuncAttributeMaxDynamicSharedMemorySize, GSMEM);
    cudaFuncSetAttribute(mma_gemm<2>, cudaFuncAttributeMaxDynamicSharedMemorySize, GSMEM);

    float *px, *pq, *pks, *pvs, *pka, *pva, *pkt, *pvt, *pada, *psc;
    __nv_bfloat16 *phh, *phl, *poh, *pol, *pfh, *pfl, *pah, *pal, *pth, *ptl, *pwh, *pwl;
    cudaGetSymbolAddress((void**)&px,  g_x);
    cudaGetSymbolAddress((void**)&pq,  g_q);
    cudaGetSymbolAddress((void**)&pks, g_ks);
    cudaGetSymbolAddress((void**)&pvs, g_vs);
    cudaGetSymbolAddress((void**)&pka, g_ka);
    cudaGetSymbolAddress((void**)&pva, g_va);
    cudaGetSymbolAddress((void**)&pkt, g_kt);
    cudaGetSymbolAddress((void**)&pvt, g_vt);
    cudaGetSymbolAddress((void**)&pada, g_ada);
    cudaGetSymbolAddress((void**)&psc,  g_sc);
    cudaGetSymbolAddress((void**)&phh, g_h_hi);   cudaGetSymbolAddress((void**)&phl, g_h_lo);
    cudaGetSymbolAddress((void**)&poh, g_o_hi);   cudaGetSymbolAddress((void**)&pol, g_o_lo);
    cudaGetSymbolAddress((void**)&pfh, g_ff_hi);  cudaGetSymbolAddress((void**)&pfl, g_ff_lo);
    cudaGetSymbolAddress((void**)&pah, g_adp_hi); cudaGetSymbolAddress((void**)&pal, g_adp_lo);
    cudaGetSymbolAddress((void**)&pth, g_tsk_hi); cudaGetSymbolAddress((void**)&ptl, g_tsk_lo);
    cudaGetSymbolAddress((void**)&pwh, g_w_hi);   cudaGetSymbolAddress((void**)&pwl, g_w_lo);

    copy_kernel<<<(MTc*Dc)/256, 256>>>(x, px, MTc*Dc);
    silu_kernel<<<(Bc*Dc)/256, 256>>>(cond, psc, Bc*Dc);
    split_tile<<<(MAc*Dc)/256, 256>>>(adp,  pah, pal);
    split_tile<<<(MSc*Dc)/256, 256>>>(task, pth, ptl);

    const float* wsrc[8] = {Wq, Wks, Wvs, Wka, Wva, Wkt, Wvt, Wo};
    for (int i = 0; i < Lc; i++) {
        size_t base = (size_t)i * WPLc;
        for (int mtx = 0; mtx < 8; mtx++)
            wprep<<<dim3(Dc/128, Dc/32), 256>>>(
                wsrc[mtx] + (size_t)i * DDc, pwh + base + (size_t)mtx * DDc,
                pwl + base + (size_t)mtx * DDc, Dc, Dc);
        wprep<<<dim3(DFFc/128, Dc/32), 256>>>(
            W1 + (size_t)i * Dc * DFFc, pwh + base + 8*DDc, pwl + base + 8*DDc, Dc, DFFc);
        wprep<<<dim3(Dc/128, DFFc/32), 256>>>(
            W2 + (size_t)i * DFFc * Dc, pwh + base + 8*DDc + (size_t)Dc*DFFc,
            pwl + base + 8*DDc + (size_t)Dc*DFFc, DFFc, Dc);
    }

    for (int i = 0; i < Lc; i++) {
        size_t wb = (size_t)i * WPLc;
        __nv_bfloat16 *wv[9], *wvl[9];
        for (int m = 0; m < 8; m++) { wv[m] = pwh + wb + (size_t)m*DDc; wvl[m] = pwl + wb + (size_t)m*DDc; }
        __nv_bfloat16* w1  = pwh + wb + 8*(size_t)DDc;
        __nv_bfloat16* w1l = pwl + wb + 8*(size_t)DDc;
        __nv_bfloat16* w2  = pwh + wb + 8*(size_t)DDc + (size_t)Dc*DFFc;
        __nv_bfloat16* w2l = pwl + wb + 8*(size_t)DDc + (size_t)Dc*DFFc;

        small_gemm_kernel<<<dim3((6*Dc)/256, Bc), 256>>>(
            psc, Wada + (size_t)i*Dc*6*Dc, bada + (size_t)i*6*Dc, pada, 6*Dc, Dc);

        ln_mod_split<<<MTc, 256>>>(px, pada, 0, Dc, phh, phl);

        mma_gemm<0><<<dim3(Dc/128, MTc/128), 256, GSMEM>>>(phh, phl, wv[0], wvl[0], bq + (size_t)i*Dc, pq,  MTc, Dc, Dc, nullptr, 0, nullptr, nullptr, nullptr);
        mma_gemm<0><<<dim3(Dc/128, MTc/128), 256, GSMEM>>>(phh, phl, wv[1], wvl[1], nullptr, pks, MTc, Dc, Dc, nullptr, 0, nullptr, nullptr, nullptr);
        mma_gemm<0><<<dim3(Dc/128, MTc/128), 256, GSMEM>>>(phh, phl, wv[2], wvl[2], nullptr, pvs, MTc, Dc, Dc, nullptr, 0, nullptr, nullptr, nullptr);
        mma_gemm<0><<<dim3(Dc/128, MAc/128), 256, GSMEM>>>(pah, pal, wv[3], wvl[3], nullptr, pka, MAc, Dc, Dc, nullptr, 0, nullptr, nullptr, nullptr);
        mma_gemm<0><<<dim3(Dc/128, MAc/128), 256, GSMEM>>>(pah, pal, wv[4], wvl[4], nullptr, pva, MAc, Dc, Dc, nullptr, 0, nullptr, nullptr, nullptr);
        mma_gemm<0><<<dim3(Dc/128, MSc/128), 256, GSMEM>>>(pth, ptl, wv[5], wvl[5], nullptr, pkt, MSc, Dc, Dc, nullptr, 0, nullptr, nullptr, nullptr);
        mma_gemm<0><<<dim3(Dc/128, MSc/128), 256, GSMEM>>>(pth, ptl, wv[6], wvl[6], nullptr, pvt, MSc, Dc, Dc, nullptr, 0, nullptr, nullptr, nullptr);

        rmsrope_kernel<<<(MTc*Hc*32)/256, 256>>>(pq,  qnw + (size_t)i*HDc, Tc,  0.125f, nullptr);
        rmsrope_kernel<<<(MTc*Hc*32)/256, 256>>>(pks, knw + (size_t)i*HDc, Tc,  1.f,    nullptr);
        rmsrope_kernel<<<(MAc*Hc*32)/256, 256>>>(pka, knw + (size_t)i*HDc, SAc, 1.f,    nullptr);
        rmsrope_kernel<<<(MSc*Hc*32)/256, 256>>>(pkt, knw + (size_t)i*HDc, STc, 1.f,    gate + i);

        flash_kernel<<<dim3(Tc/128, Bc*Hc), 128>>>(pq, pks, pvs, pka, pva, pkt, pvt, poh, pol);

        mma_gemm<2><<<dim3(Dc/128, MTc/128), 256, GSMEM>>>(poh, pol, wv[7], wvl[7], bo + (size_t)i*Dc, nullptr,
                                                           MTc, Dc, Dc, pada + 2*Dc, 6*Dc, px, nullptr, nullptr);

        ln_mod_split<<<MTc, 256>>>(px, pada, 3*Dc, 4*Dc, phh, phl);

        mma_gemm<1><<<dim3(DFFc/128, MTc/128), 256, GSMEM>>>(phh, phl, w1, w1l, b1 + (size_t)i*DFFc, nullptr,
                                                             MTc, DFFc, Dc, nullptr, 0, nullptr, pfh, pfl);

        mma_gemm<2><<<dim3(Dc/128, MTc/128), 256, GSMEM>>>(pfh, pfl, w2, w2l, b2 + (size_t)i*Dc, nullptr,
                                                           MTc, Dc, DFFc, pada + 5*Dc, 6*Dc, px, nullptr, nullptr);
    }

    final_kernel<<<MTc, 256>>>(px, lnfw, lnfb, Wout, bout, out);
}

// round 8
// speedup vs baseline: 1.4760x; 1.2180x over previous
#include <cuda_runtime.h>
#include <cuda_fp16.h>
#include <math.h>
#include <stdint.h>

#define Lc 6
#define Bc 32
#define Tc 256
#define SAc 512
#define STc 128
#define Dc 1024
#define Hc 16
#define HDc 64
#define DFFc 4096
#define OUTc 3
#define MTc (Bc*Tc)
#define MAc (Bc*SAc)
#define MSc (Bc*STc)
#define DDc (Dc*Dc)
#define WPLc (8*DDc + Dc*DFFc + DFFc*Dc)

__device__ float g_x[MTc*Dc];
__device__ float g_q[MTc*Dc];
__device__ float g_ks[MTc*Dc];
__device__ float g_vs[MTc*Dc];
__device__ float g_ka[MAc*Dc];
__device__ float g_va[MAc*Dc];
__device__ float g_kt[MSc*Dc];
__device__ float g_vt[MSc*Dc];
__device__ float g_ada[Bc*6*Dc];
__device__ float g_sc[Bc*Dc];

__device__ __align__(256) __half g_h[MTc*Dc];
__device__ __align__(256) __half g_o[MTc*Dc];
__device__ __align__(256) __half g_ff[MTc*DFFc];
__device__ __align__(256) __half g_adp[MAc*Dc];
__device__ __align__(256) __half g_tsk[MSc*Dc];
__device__ __align__(256) __half g_w_hi[Lc*WPLc], g_w_lo[Lc*WPLc];

__device__ __forceinline__ uint32_t smem_u32(const void* p) {
    uint32_t a;
    asm("{ .reg .u64 t; cvta.to.shared.u64 t, %1; cvt.u32.u64 %0, t; }" : "=r"(a) : "l"(p));
    return a;
}
#define MBAR_INIT(a, n) asm volatile("mbarrier.init.shared.b64 [%0], %1;" :: "r"(a), "r"(n) : "memory")
#define MBAR_EXPECT(a, tx) asm volatile("mbarrier.arrive.expect_tx.shared.b64 _, [%0], %1;" :: "r"(a), "r"(tx) : "memory")
#define MBAR_ARRIVE(a) asm volatile("mbarrier.arrive.shared.b64 _, [%0];" :: "r"(a) : "memory")
#define MBAR_WAIT(a, ph) do { \
    uint32_t _m = (a), _p = (ph), _d; \
    asm volatile("{ .reg .pred p; mbarrier.try_wait.parity.acquire.cta.shared::cta.b64 p, [%1], %2; selp.b32 %0,1,0,p; }" \
        : "=r"(_d) : "r"(_m), "r"(_p) : "memory"); \
    if (!_d) { \
        asm volatile("{ .reg .pred P1; WL_%=: mbarrier.try_wait.parity.acquire.cta.shared::cta.b64 P1, [%0], %1, 0x989680; @P1 bra.uni WD_%=; bra.uni WL_%=; WD_%=: }" \
            :: "r"(_m), "r"(_p) : "memory"); \
    } } while (0)
#define BULK8K(dst, src, bar) asm volatile( \
    "cp.async.bulk.shared::cluster.global.mbarrier::complete_tx::bytes [%0], [%1], 8192, [%2];" \
    :: "r"(dst), "l"(src), "r"(bar) : "memory")
#define FENCE_ASYNC() asm volatile("fence.proxy.async.shared::cta;" ::: "memory")
#define LDSM4(r, a) asm volatile( \
    "ldmatrix.sync.aligned.m8n8.x4.shared.b16 {%0,%1,%2,%3}, [%4];" \
    : "=r"((r)[0]), "=r"((r)[1]), "=r"((r)[2]), "=r"((r)[3]) : "r"(a))

__device__ __forceinline__ void mma_f16(float* c, const uint32_t* a, const uint32_t* b) {
    asm volatile(
        "mma.sync.aligned.m16n8k16.row.col.f32.f16.f16.f32 "
        "{%0,%1,%2,%3}, {%4,%5,%6,%7}, {%8,%9}, {%0,%1,%2,%3};"
        : "+f"(c[0]), "+f"(c[1]), "+f"(c[2]), "+f"(c[3])
        : "r"(a[0]), "r"(a[1]), "r"(a[2]), "r"(a[3]), "r"(b[0]), "r"(b[1]));
}
__device__ __forceinline__ float gelu_t(float c) {
    float t = 0.7978845608028654f * (c + 0.044715f * c * c * c);
    return 0.5f * c * (1.f + tanhf(t));
}
// (row,col) of [M,Ncols] -> tile-major swizzled element offset (128x32 tiles, 8KB)
__device__ __forceinline__ size_t tile_off(int row, int col, int Ncols) {
    int r = row & 127;
    int cp = ((col >> 3) & 3) ^ ((r >> 1) & 3);
    return ((size_t)(row >> 7) * (Ncols >> 5) + (col >> 5)) * 4096 + r * 32 + cp * 8 + (col & 7);
}

// ---- fp16 2-pass MMA GEMM (A single fp16, W = Wh+Wl), 6-stage bulk ring ----
// EPI 0: C=acc+bias f32 | EPI 1: gelu->fp16 tile-major | EPI 2: X += gmod*(acc+bias)
#define NST 6
#define STB 24576
#define GSMEM (NST*STB + 128)
template <int EPI>
__global__ __launch_bounds__(256) void mma_gemm(
    const __half* __restrict__ A, const __half* __restrict__ Bh, const __half* __restrict__ Bl,
    const float* __restrict__ bias, float* __restrict__ C, int M, int N, int K,
    const float* __restrict__ gmod, int gstride, float* __restrict__ X,
    __half* __restrict__ Cout)
{
    extern __shared__ __align__(128) char smem[];
    const int tid = threadIdx.x;
    const uint32_t sb = smem_u32(smem);
    const uint32_t mbF = sb + NST * STB;
    const uint32_t mbE = mbF + 8 * NST;
    const int Kt = K >> 5;
    const size_t abase = (size_t)blockIdx.y * Kt * 4096;
    const size_t bbase = (size_t)blockIdx.x * Kt * 4096;

    if (tid == 0) {
        for (int s = 0; s < NST; s++) { MBAR_INIT(mbF + 8 * s, 1); MBAR_INIT(mbE + 8 * s, 256); }
        FENCE_ASYNC();
    }
    __syncthreads();

    auto issue = [&](int slot, int c) {
        uint32_t d = sb + slot * STB;
        uint32_t bar = mbF + 8 * slot;
        MBAR_EXPECT(bar, (uint32_t)STB);
        BULK8K(d,         A  + abase + (size_t)c * 4096, bar);
        BULK8K(d + 8192,  Bh + bbase + (size_t)c * 4096, bar);
        BULK8K(d + 16384, Bl + bbase + (size_t)c * 4096, bar);
    };
    if (tid == 0)
        for (int s = 0; s < NST; s++) issue(s, s);

    const int w = tid >> 5, lane = tid & 31;
    const int wm = w >> 2, wn = w & 3;
    const int g = lane >> 2, t = lane & 3;

    const int ra  = (lane & 7) + ((lane >> 3) & 1) * 8;
    const int sa  = lane >> 4;
    const int s3a = (ra >> 1) & 3;
    const int rb  = (lane & 7) + (lane >> 4) * 8;
    const int sbk = (lane >> 3) & 1;
    const int s3b = (rb >> 1) & 3;

    uint32_t aoff[2][4], boff[2][2];
    #pragma unroll
    for (int ks = 0; ks < 2; ks++) {
        #pragma unroll
        for (int mt = 0; mt < 4; mt++)
            aoff[ks][mt] = (uint32_t)((wm * 64 + mt * 16 + ra) * 64 + (((ks * 2 + sa) ^ s3a) * 16));
        #pragma unroll
        for (int np = 0; np < 2; np++)
            boff[ks][np] = (uint32_t)((wn * 32 + np * 16 + rb) * 64 + (((ks * 2 + sbk) ^ s3b) * 16));
    }

    float acc[4][4][4];
    #pragma unroll
    for (int i = 0; i < 4; i++)
        #pragma unroll
        for (int j = 0; j < 4; j++)
            #pragma unroll
            for (int e = 0; e < 4; e++) acc[i][j][e] = 0.f;

    int slot = 0, rph = 0;
    for (int c = 0; c < Kt; c++) {
        MBAR_WAIT(mbF + 8 * slot, rph);
        const uint32_t base = sb + slot * STB;
        #pragma unroll
        for (int ks = 0; ks < 2; ks++) {
            uint32_t a4[4][4], bh4[2][4], bl4[2][4];
            #pragma unroll
            for (int mt = 0; mt < 4; mt++) LDSM4(a4[mt], base + aoff[ks][mt]);
            #pragma unroll
            for (int np = 0; np < 2; np++) {
                LDSM4(bh4[np], base + 8192  + boff[ks][np]);
                LDSM4(bl4[np], base + 16384 + boff[ks][np]);
            }
            #pragma unroll
            for (int mt = 0; mt < 4; mt++)
                #pragma unroll
                for (int nt = 0; nt < 4; nt++)
                    mma_f16(acc[mt][nt], a4[mt], &bh4[nt >> 1][(nt & 1) * 2]);
            #pragma unroll
            for (int mt = 0; mt < 4; mt++)
                #pragma unroll
                for (int nt = 0; nt < 4; nt++)
                    mma_f16(acc[mt][nt], a4[mt], &bl4[nt >> 1][(nt & 1) * 2]);
        }
        MBAR_ARRIVE(mbE + 8 * slot);
        if (tid == 0 && c + NST < Kt) {
            MBAR_WAIT(mbE + 8 * slot, rph);
            FENCE_ASYNC();
            issue(slot, c + NST);
        }
        if (++slot == NST) { slot = 0; rph ^= 1; }
    }

    const int row0 = blockIdx.y * 128, col0 = blockIdx.x * 128;
    #pragma unroll
    for (int mt = 0; mt < 4; mt++) {
        const int row = row0 + wm * 64 + mt * 16 + g;
        #pragma unroll
        for (int nt = 0; nt < 4; nt++) {
            const int col = col0 + wn * 32 + nt * 8 + 2 * t;
            const float* a = acc[mt][nt];
            const float b0v = bias ? bias[col] : 0.f;
            const float b1v = bias ? bias[col + 1] : 0.f;
            const float v0 = a[0] + b0v, v1 = a[1] + b1v;
            const float v2 = a[2] + b0v, v3 = a[3] + b1v;
            if (EPI == 0) {
                *(float2*)(C + (size_t)row * N + col)       = make_float2(v0, v1);
                *(float2*)(C + (size_t)(row + 8) * N + col) = make_float2(v2, v3);
            } else if (EPI == 1) {
                size_t o0 = tile_off(row, col, N), o1 = tile_off(row + 8, col, N);
                *(__half2*)(Cout + o0) = __floats2half2_rn(gelu_t(v0), gelu_t(v1));
                *(__half2*)(Cout + o1) = __floats2half2_rn(gelu_t(v2), gelu_t(v3));
            } else {
                const int bb = row >> 8;
                const float* gm = gmod + (size_t)bb * gstride;
                float2 x0 = *(float2*)(X + (size_t)row * N + col);
                float2 x1 = *(float2*)(X + (size_t)(row + 8) * N + col);
                x0.x += gm[col] * v0;  x0.y += gm[col + 1] * v1;
                x1.x += gm[col] * v2;  x1.y += gm[col + 1] * v3;
                *(float2*)(X + (size_t)row * N + col)       = x0;
                *(float2*)(X + (size_t)(row + 8) * N + col) = x1;
            }
        }
    }
}

// W[K,N] f32 -> tile-major swizzled fp16 hi/lo of Wt[N,K]
__global__ __launch_bounds__(256) void wprep(const float* __restrict__ W,
    __half* __restrict__ Whi, __half* __restrict__ Wlo, int K, int N) {
    __shared__ float s[32 * 128];
    const int i = blockIdx.x, j = blockIdx.y;
    #pragma unroll
    for (int e = 0; e < 16; e++) {
        int idx = threadIdx.x + e * 256;
        int kk = idx >> 7, r = idx & 127;
        s[kk * 128 + r] = W[(size_t)(j * 32 + kk) * N + i * 128 + r];
    }
    __syncthreads();
    const size_t tbase = ((size_t)i * (K >> 5) + j) * 4096;
    #pragma unroll
    for (int e = 0; e < 2; e++) {
        int q = threadIdx.x * 2 + e;
        int r = q >> 2, cp = q & 3;
        int c = cp ^ ((r >> 1) & 3);
        uint32_t hw[4], lw[4];
        #pragma unroll
        for (int u = 0; u < 4; u++) {
            float v0 = s[(c * 8 + 2 * u) * 128 + r];
            float v1 = s[(c * 8 + 2 * u + 1) * 128 + r];
            __half h0 = __float2half(v0), h1 = __float2half(v1);
            __half2 hp = __halves2half2(h0, h1);
            __half2 lp = __floats2half2_rn(v0 - __half2float(h0), v1 - __half2float(h1));
            hw[u] = *(uint32_t*)&hp;
            lw[u] = *(uint32_t*)&lp;
        }
        *(uint4*)(Whi + tbase + r * 32 + cp * 8) = make_uint4(hw[0], hw[1], hw[2], hw[3]);
        *(uint4*)(Wlo + tbase + r * 32 + cp * 8) = make_uint4(lw[0], lw[1], lw[2], lw[3]);
    }
}

// fp32 [M,1024] row-major -> tile-major fp16
__global__ void split_tile(const float* __restrict__ s, __half* __restrict__ hi) {
    int idx = blockIdx.x * 256 + threadIdx.x;
    int row = idx >> 10, d = idx & 1023;
    hi[tile_off(row, d, Dc)] = __float2half(s[idx]);
}

__global__ void copy_kernel(const float* __restrict__ src, float* __restrict__ dst, int n) {
    int i = blockIdx.x * blockDim.x + threadIdx.x;
    if (i < n) dst[i] = src[i];
}
__global__ void silu_kernel(const float* __restrict__ c, float* __restrict__ out, int n) {
    int i = blockIdx.x * blockDim.x + threadIdx.x;
    if (i < n) { float x = c[i]; out[i] = x / (1.f + expf(-x)); }
}
__device__ __forceinline__ float block_reduce_sum(float v, float* red) {
    int tid = threadIdx.x;
    red[tid] = v;
    __syncthreads();
    #pragma unroll
    for (int s = 128; s > 0; s >>= 1) {
        if (tid < s) red[tid] += red[tid + s];
        __syncthreads();
    }
    float r = red[0];
    __syncthreads();
    return r;
}

__global__ void ln_mod(const float* __restrict__ x, const float* __restrict__ ada,
                       int off_shift, int off_scale, __half* __restrict__ hi) {
    __shared__ float red[256];
    int row = blockIdx.x, b = row / Tc, tid = threadIdx.x;
    const float* xr = x + (size_t)row * Dc;
    float v[4], s = 0.f;
    #pragma unroll
    for (int i = 0; i < 4; i++) { v[i] = xr[tid + i * 256]; s += v[i]; }
    float mean = block_reduce_sum(s, red) * (1.f / 1024.f);
    float sq = 0.f;
    #pragma unroll
    for (int i = 0; i < 4; i++) { float d = v[i] - mean; sq += d * d; }
    float rstd = rsqrtf(block_reduce_sum(sq, red) * (1.f / 1024.f) + 1e-5f);
    const float* ab = ada + (size_t)b * 6 * Dc;
    #pragma unroll
    for (int i = 0; i < 4; i++) {
        int d = tid + i * 256;
        float o = (v[i] - mean) * rstd * (1.f + ab[off_scale + d]) + ab[off_shift + d];
        hi[tile_off(row, d, Dc)] = __float2half(o);
    }
}

__global__ void rmsrope_kernel(float* __restrict__ t, const float* __restrict__ w,
                               int S, float cmul, const float* __restrict__ gate) {
    int warp = (blockIdx.x * blockDim.x + threadIdx.x) >> 5;
    int lane = threadIdx.x & 31;
    int s = (warp / Hc) % S;
    float* p = t + (size_t)warp * HDc;
    float x0 = p[lane], x1 = p[lane + 32];
    float ss = x0 * x0 + x1 * x1;
    #pragma unroll
    for (int o = 16; o; o >>= 1) ss += __shfl_xor_sync(0xffffffffu, ss, o);
    float inv = rsqrtf(ss * (1.f / 64.f) + 1e-6f);
    x0 = x0 * inv * w[lane];
    x1 = x1 * inv * w[lane + 32];
    float fr = (float)s * expf(-(float)lane * 0.28782313662425575f);
    float c = cosf(fr), sn = sinf(fr);
    float mult = cmul;
    if (gate) mult *= 1.f / (1.f + expf(-gate[0]));
    p[lane]      = (x0 * c - x1 * sn) * mult;
    p[lane + 32] = (x1 * c + x0 * sn) * mult;
}

__global__ void small_gemm_kernel(const float* __restrict__ A, const float* __restrict__ W,
                                  const float* __restrict__ bias, float* __restrict__ C,
                                  int Nn, int Kk) {
    int n = blockIdx.x * blockDim.x + threadIdx.x;
    int b = blockIdx.y;
    if (n >= Nn) return;
    const float* a = A + (size_t)b * Kk;
    float acc = 0.f;
    #pragma unroll 4
    for (int k = 0; k < Kk; k++) acc += a[k] * W[(size_t)k * Nn + n];
    C[(size_t)b * Nn + n] = acc + (bias ? bias[n] : 0.f);
}

// flash attention fp32, output tile-major fp16
__global__ __launch_bounds__(128) void flash_kernel(
    const float* __restrict__ q,
    const float* __restrict__ ks, const float* __restrict__ vs,
    const float* __restrict__ ka, const float* __restrict__ va,
    const float* __restrict__ kt, const float* __restrict__ vt,
    __half* __restrict__ oh)
{
    __shared__ float4 Ks4[32][16];
    __shared__ float4 Vs4[32][16];
    int tid = threadIdx.x, bh = blockIdx.y;
    int b = bh / Hc, h = bh % Hc;
    int qi = blockIdx.x * 128 + tid;

    float qr[64], oa[64];
    const float* qp = q + (size_t)(b * Tc + qi) * Dc + h * HDc;
    #pragma unroll
    for (int j = 0; j < 16; j++) {
        float4 v4 = *(const float4*)&qp[j * 4];
        qr[4*j] = v4.x; qr[4*j+1] = v4.y; qr[4*j+2] = v4.z; qr[4*j+3] = v4.w;
    }
    #pragma unroll
    for (int d = 0; d < 64; d++) oa[d] = 0.f;
    float m = -1e30f, l = 0.f;

    const float* Kseg[3] = {ks, ka, kt};
    const float* Vseg[3] = {vs, va, vt};
    const int Slen[3] = {Tc, SAc, STc};

    #pragma unroll
    for (int seg = 0; seg < 3; seg++) {
        const float* K = Kseg[seg];
        const float* V = Vseg[seg];
        int S = Slen[seg];
        for (int s0 = 0; s0 < S; s0 += 32) {
            __syncthreads();
            #pragma unroll
            for (int i = 0; i < 4; i++) {
                int idx = tid + i * 128;
                int r = idx >> 4, cc = idx & 15;
                size_t base = (size_t)(b * S + s0 + r) * Dc + h * HDc + cc * 4;
                Ks4[r][cc] = *(const float4*)&K[base];
                Vs4[r][cc] = *(const float4*)&V[base];
            }
            __syncthreads();
            float sc[32], tmax = -1e30f;
            #pragma unroll
            for (int s = 0; s < 32; s++) {
                float d0 = 0.f, d1 = 0.f, d2 = 0.f, d3 = 0.f;
                #pragma unroll
                for (int j = 0; j < 16; j++) {
                    float4 kv = Ks4[s][j];
                    d0 = fmaf(qr[4*j],   kv.x, d0);
                    d1 = fmaf(qr[4*j+1], kv.y, d1);
                    d2 = fmaf(qr[4*j+2], kv.z, d2);
                    d3 = fmaf(qr[4*j+3], kv.w, d3);
                }
                sc[s] = (d0 + d1) + (d2 + d3);
                tmax = fmaxf(tmax, sc[s]);
            }
            float mnew = fmaxf(m, tmax);
            float corr = __expf(m - mnew);
            l *= corr;
            #pragma unroll
            for (int d = 0; d < 64; d++) oa[d] *= corr;
            #pragma unroll
            for (int s = 0; s < 32; s++) {
                float p = __expf(sc[s] - mnew);
                l += p;
                #pragma unroll
                for (int j = 0; j < 16; j++) {
                    float4 vv = Vs4[s][j];
                    oa[4*j]   = fmaf(p, vv.x, oa[4*j]);
                    oa[4*j+1] = fmaf(p, vv.y, oa[4*j+1]);
                    oa[4*j+2] = fmaf(p, vv.z, oa[4*j+2]);
                    oa[4*j+3] = fmaf(p, vv.w, oa[4*j+3]);
                }
            }
            m = mnew;
        }
    }
    float invl = 1.f / l;
    int orow = b * Tc + qi;
    #pragma unroll
    for (int d = 0; d < 64; d++)
        oh[tile_off(orow, h * HDc + d, Dc)] = __float2half(oa[d] * invl);
}

__global__ void final_kernel(const float* __restrict__ x, const float* __restrict__ lw,
                             const float* __restrict__ lb, const float* __restrict__ Wout,
                             const float* __restrict__ bout, float* __restrict__ out) {
    __shared__ float red[256];
    int row = blockIdx.x, tid = threadIdx.x;
    const float* xr = x + (size_t)row * Dc;
    float v[4], s = 0.f;
    #pragma unroll
    for (int i = 0; i < 4; i++) { v[i] = xr[tid + i * 256]; s += v[i]; }
    float mean = block_reduce_sum(s, red) * (1.f / 1024.f);
    float sq = 0.f;
    #pragma unroll
    for (int i = 0; i < 4; i++) { float d = v[i] - mean; sq += d * d; }
    float rstd = rsqrtf(block_reduce_sum(sq, red) * (1.f / 1024.f) + 1e-5f);
    float p0 = 0.f, p1 = 0.f, p2 = 0.f;
    #pragma unroll
    for (int i = 0; i < 4; i++) {
        int d = tid + i * 256;
        float y = (v[i] - mean) * rstd * lw[d] + lb[d];
        p0 = fmaf(y, Wout[d * OUTc + 0], p0);
        p1 = fmaf(y, Wout[d * OUTc + 1], p1);
        p2 = fmaf(y, Wout[d * OUTc + 2], p2);
    }
    p0 = block_reduce_sum(p0, red);
    p1 = block_reduce_sum(p1, red);
    p2 = block_reduce_sum(p2, red);
    if (tid == 0) {
        out[row * OUTc + 0] = p0 + bout[0];
        out[row * OUTc + 1] = p1 + bout[1];
        out[row * OUTc + 2] = p2 + bout[2];
    }
}

extern "C" void kernel_launch(void* const* d_in, const int* in_sizes, int n_in,
                              void* d_out, int out_size)
{
    (void)in_sizes; (void)n_in; (void)out_size;
    const float* x    = (const float*)d_in[0];
    const float* cond = (const float*)d_in[1];
    const float* adp  = (const float*)d_in[2];
    const float* task = (const float*)d_in[3];
    const float* Wq   = (const float*)d_in[4];
    const float* bq   = (const float*)d_in[5];
    const float* Wks  = (const float*)d_in[6];
    const float* Wvs  = (const float*)d_in[7];
    const float* Wka  = (const float*)d_in[8];
    const float* Wva  = (const float*)d_in[9];
    const float* Wkt  = (const float*)d_in[10];
    const float* Wvt  = (const float*)d_in[11];
    const float* Wo   = (const float*)d_in[12];
    const float* bo   = (const float*)d_in[13];
    const float* qnw  = (const float*)d_in[14];
    const float* knw  = (const float*)d_in[15];
    const float* gate = (const float*)d_in[16];
    const float* Wada = (const float*)d_in[17];
    const float* bada = (const float*)d_in[18];
    const float* W1   = (const float*)d_in[19];
    const float* b1   = (const float*)d_in[20];
    const float* W2   = (const float*)d_in[21];
    const float* b2   = (const float*)d_in[22];
    const float* lnfw = (const float*)d_in[23];
    const float* lnfb = (const float*)d_in[24];
    const float* Wout = (const float*)d_in[25];
    const float* bout = (const float*)d_in[26];
    float* out = (float*)d_out;

    cudaFuncSetAttribute(mma_gemm<0>, cudaFuncAttributeMaxDynamicSharedMemorySize, GSMEM);
    cudaFuncSetAttribute(mma_gemm<1>, cudaFuncAttributeMaxDynamicSharedMemorySize, GSMEM);
    cudaFuncSetAttribute(mma_gemm<2>, cudaFuncAttributeMaxDynamicSharedMemorySize, GSMEM);

    float *px, *pq, *pks, *pvs, *pka, *pva, *pkt, *pvt, *pada, *psc;
    __half *ph, *po, *pf, *pa, *pt, *pwh, *pwl;
    cudaGetSymbolAddress((void**)&px,  g_x);
    cudaGetSymbolAddress((void**)&pq,  g_q);
    cudaGetSymbolAddress((void**)&pks, g_ks);
    cudaGetSymbolAddress((void**)&pvs, g_vs);
    cudaGetSymbolAddress((void**)&pka, g_ka);
    cudaGetSymbolAddress((void**)&pva, g_va);
    cudaGetSymbolAddress((void**)&pkt, g_kt);
    cudaGetSymbolAddress((void**)&pvt, g_vt);
    cudaGetSymbolAddress((void**)&pada, g_ada);
    cudaGetSymbolAddress((void**)&psc,  g_sc);
    cudaGetSymbolAddress((void**)&ph, g_h);
    cudaGetSymbolAddress((void**)&po, g_o);
    cudaGetSymbolAddress((void**)&pf, g_ff);
    cudaGetSymbolAddress((void**)&pa, g_adp);
    cudaGetSymbolAddress((void**)&pt, g_tsk);
    cudaGetSymbolAddress((void**)&pwh, g_w_hi);
    cudaGetSymbolAddress((void**)&pwl, g_w_lo);

    copy_kernel<<<(MTc*Dc)/256, 256>>>(x, px, MTc*Dc);
    silu_kernel<<<(Bc*Dc)/256, 256>>>(cond, psc, Bc*Dc);
    split_tile<<<(MAc*Dc)/256, 256>>>(adp,  pa);
    split_tile<<<(MSc*Dc)/256, 256>>>(task, pt);

    const float* wsrc[8] = {Wq, Wks, Wvs, Wka, Wva, Wkt, Wvt, Wo};
    for (int i = 0; i < Lc; i++) {
        size_t base = (size_t)i * WPLc;
        for (int mtx = 0; mtx < 8; mtx++)
            wprep<<<dim3(Dc/128, Dc/32), 256>>>(
                wsrc[mtx] + (size_t)i * DDc, pwh + base + (size_t)mtx * DDc,
                pwl + base + (size_t)mtx * DDc, Dc, Dc);
        wprep<<<dim3(DFFc/128, Dc/32), 256>>>(
            W1 + (size_t)i * Dc * DFFc, pwh + base + 8*DDc, pwl + base + 8*DDc, Dc, DFFc);
        wprep<<<dim3(Dc/128, DFFc/32), 256>>>(
            W2 + (size_t)i * DFFc * Dc, pwh + base + 8*DDc + (size_t)Dc*DFFc,
            pwl + base + 8*DDc + (size_t)Dc*DFFc, DFFc, Dc);
    }

    for (int i = 0; i < Lc; i++) {
        size_t wb = (size_t)i * WPLc;
        __half *wv[8], *wvl[8];
        for (int m = 0; m < 8; m++) { wv[m] = pwh + wb + (size_t)m*DDc; wvl[m] = pwl + wb + (size_t)m*DDc; }
        __half* w1  = pwh + wb + 8*(size_t)DDc;
        __half* w1l = pwl + wb + 8*(size_t)DDc;
        __half* w2  = pwh + wb + 8*(size_t)DDc + (size_t)Dc*DFFc;
        __half* w2l = pwl + wb + 8*(size_t)DDc + (size_t)Dc*DFFc;

        small_gemm_kernel<<<dim3((6*Dc)/256, Bc), 256>>>(
            psc, Wada + (size_t)i*Dc*6*Dc, bada + (size_t)i*6*Dc, pada, 6*Dc, Dc);

        ln_mod<<<MTc, 256>>>(px, pada, 0, Dc, ph);

        mma_gemm<0><<<dim3(Dc/128, MTc/128), 256, GSMEM>>>(ph, wv[0], wvl[0], bq + (size_t)i*Dc, pq,  MTc, Dc, Dc, nullptr, 0, nullptr, nullptr);
        mma_gemm<0><<<dim3(Dc/128, MTc/128), 256, GSMEM>>>(ph, wv[1], wvl[1], nullptr, pks, MTc, Dc, Dc, nullptr, 0, nullptr, nullptr);
        mma_gemm<0><<<dim3(Dc/128, MTc/128), 256, GSMEM>>>(ph, wv[2], wvl[2], nullptr, pvs, MTc, Dc, Dc, nullptr, 0, nullptr, nullptr);
        mma_gemm<0><<<dim3(Dc/128, MAc/128), 256, GSMEM>>>(pa, wv[3], wvl[3], nullptr, pka, MAc, Dc, Dc, nullptr, 0, nullptr, nullptr);
        mma_gemm<0><<<dim3(Dc/128, MAc/128), 256, GSMEM>>>(pa, wv[4], wvl[4], nullptr, pva, MAc, Dc, Dc, nullptr, 0, nullptr, nullptr);
        mma_gemm<0><<<dim3(Dc/128, MSc/128), 256, GSMEM>>>(pt, wv[5], wvl[5], nullptr, pkt, MSc, Dc, Dc, nullptr, 0, nullptr, nullptr);
        mma_gemm<0><<<dim3(Dc/128, MSc/128), 256, GSMEM>>>(pt, wv[6], wvl[6], nullptr, pvt, MSc, Dc, Dc, nullptr, 0, nullptr, nullptr);

        rmsrope_kernel<<<(MTc*Hc*32)/256, 256>>>(pq,  qnw + (size_t)i*HDc, Tc,  0.125f, nullptr);
        rmsrope_kernel<<<(MTc*Hc*32)/256, 256>>>(pks, knw + (size_t)i*HDc, Tc,  1.f,    nullptr);
        rmsrope_kernel<<<(MAc*Hc*32)/256, 256>>>(pka, knw + (size_t)i*HDc, SAc, 1.f,    nullptr);
        rmsrope_kernel<<<(MSc*Hc*32)/256, 256>>>(pkt, knw + (size_t)i*HDc, STc, 1.f,    gate + i);

        flash_kernel<<<dim3(Tc/128, Bc*Hc), 128>>>(pq, pks, pvs, pka, pva, pkt, pvt, po);

        mma_gemm<2><<<dim3(Dc/128, MTc/128), 256, GSMEM>>>(po, wv[7], wvl[7], bo + (size_t)i*Dc, nullptr,
                                                           MTc, Dc, Dc, pada + 2*Dc, 6*Dc, px, nullptr);

        ln_mod<<<MTc, 256>>>(px, pada, 3*Dc, 4*Dc, ph);

        mma_gemm<1><<<dim3(DFFc/128, MTc/128), 256, GSMEM>>>(ph, w1, w1l, b1 + (size_t)i*DFFc, nullptr,
                                                             MTc, DFFc, Dc, nullptr, 0, nullptr, pf);

        mma_gemm<2><<<dim3(Dc/128, MTc/128), 256, GSMEM>>>(pf, w2, w2l, b2 + (size_t)i*Dc, nullptr,
                                                           MTc, Dc, DFFc, pada + 5*Dc, 6*Dc, px, nullptr);
    }

    final_kernel<<<MTc, 256>>>(px, lnfw, lnfb, Wout, bout, out);
}

// round 9
// speedup vs baseline: 1.6985x; 1.1507x over previous
#include <cuda_runtime.h>
#include <cuda_fp16.h>
#include <math.h>
#include <stdint.h>

#define Lc 6
#define Bc 32
#define Tc 256
#define SAc 512
#define STc 128
#define Dc 1024
#define Hc 16
#define HDc 64
#define DFFc 4096
#define OUTc 3
#define MTc (Bc*Tc)
#define MAc (Bc*SAc)
#define MSc (Bc*STc)
#define DDc (Dc*Dc)
#define WPLc (8*DDc + Dc*DFFc + DFFc*Dc)

__device__ float g_x[MTc*Dc];
__device__ float g_q[MTc*Dc];
__device__ float g_ks[MTc*Dc];
__device__ float g_vs[MTc*Dc];
__device__ float g_ka[MAc*Dc];
__device__ float g_va[MAc*Dc];
__device__ float g_kt[MSc*Dc];
__device__ float g_vt[MSc*Dc];
__device__ float g_ada[Bc*6*Dc];
__device__ float g_sc[Bc*Dc];

__device__ __align__(256) __half g_h[MTc*Dc];
__device__ __align__(256) __half g_o[MTc*Dc];
__device__ __align__(256) __half g_ff[MTc*DFFc];
__device__ __align__(256) __half g_adp[MAc*Dc];
__device__ __align__(256) __half g_tsk[MSc*Dc];
__device__ __align__(256) __half g_w[Lc*WPLc];

__device__ __forceinline__ uint32_t smem_u32(const void* p) {
    uint32_t a;
    asm("{ .reg .u64 t; cvta.to.shared.u64 t, %1; cvt.u32.u64 %0, t; }" : "=r"(a) : "l"(p));
    return a;
}
#define MBAR_INIT(a, n) asm volatile("mbarrier.init.shared.b64 [%0], %1;" :: "r"(a), "r"(n) : "memory")
#define MBAR_EXPECT(a, tx) asm volatile("mbarrier.arrive.expect_tx.shared.b64 _, [%0], %1;" :: "r"(a), "r"(tx) : "memory")
#define MBAR_ARRIVE(a) asm volatile("mbarrier.arrive.shared.b64 _, [%0];" :: "r"(a) : "memory")
#define MBAR_WAIT(a, ph) do { \
    uint32_t _m = (a), _p = (ph), _d; \
    asm volatile("{ .reg .pred p; mbarrier.try_wait.parity.acquire.cta.shared::cta.b64 p, [%1], %2; selp.b32 %0,1,0,p; }" \
        : "=r"(_d) : "r"(_m), "r"(_p) : "memory"); \
    if (!_d) { \
        asm volatile("{ .reg .pred P1; WL_%=: mbarrier.try_wait.parity.acquire.cta.shared::cta.b64 P1, [%0], %1, 0x989680; @P1 bra.uni WD_%=; bra.uni WL_%=; WD_%=: }" \
            :: "r"(_m), "r"(_p) : "memory"); \
    } } while (0)
#define BULK8K(dst, src, bar) asm volatile( \
    "cp.async.bulk.shared::cluster.global.mbarrier::complete_tx::bytes [%0], [%1], 8192, [%2];" \
    :: "r"(dst), "l"(src), "r"(bar) : "memory")
#define FENCE_ASYNC() asm volatile("fence.proxy.async.shared::cta;" ::: "memory")
#define LDSM4(r, a) asm volatile( \
    "ldmatrix.sync.aligned.m8n8.x4.shared.b16 {%0,%1,%2,%3}, [%4];" \
    : "=r"((r)[0]), "=r"((r)[1]), "=r"((r)[2]), "=r"((r)[3]) : "r"(a))

__device__ __forceinline__ void mma_f16(float* c, const uint32_t* a, const uint32_t* b) {
    asm volatile(
        "mma.sync.aligned.m16n8k16.row.col.f32.f16.f16.f32 "
        "{%0,%1,%2,%3}, {%4,%5,%6,%7}, {%8,%9}, {%0,%1,%2,%3};"
        : "+f"(c[0]), "+f"(c[1]), "+f"(c[2]), "+f"(c[3])
        : "r"(a[0]), "r"(a[1]), "r"(a[2]), "r"(a[3]), "r"(b[0]), "r"(b[1]));
}
__device__ __forceinline__ float gelu_t(float c) {
    float t = 0.7978845608028654f * (c + 0.044715f * c * c * c);
    return 0.5f * c * (1.f + tanhf(t));
}
// (row,col) of [M,Ncols] -> tile-major swizzled element offset (128x32 tiles, 8KB)
__device__ __forceinline__ size_t tile_off(int row, int col, int Ncols) {
    int r = row & 127;
    int cp = ((col >> 3) & 3) ^ ((r >> 1) & 3);
    return ((size_t)(row >> 7) * (Ncols >> 5) + (col >> 5)) * 4096 + r * 32 + cp * 8 + (col & 7);
}

// ---- fp16 single-pass MMA GEMM, 8-stage bulk ring ----
// EPI 0: C=acc+bias f32 | EPI 1: gelu->fp16 tile-major | EPI 2: X += gmod*(acc+bias)
#define NST 8
#define STB 16384
#define GSMEM (NST*STB + 128)
template <int EPI>
__global__ __launch_bounds__(256) void mma_gemm(
    const __half* __restrict__ A, const __half* __restrict__ Bw,
    const float* __restrict__ bias, float* __restrict__ C, int M, int N, int K,
    const float* __restrict__ gmod, int gstride, float* __restrict__ X,
    __half* __restrict__ Cout)
{
    extern __shared__ __align__(128) char smem[];
    const int tid = threadIdx.x;
    const uint32_t sb = smem_u32(smem);
    const uint32_t mbF = sb + NST * STB;
    const uint32_t mbE = mbF + 8 * NST;
    const int Kt = K >> 5;
    const size_t abase = (size_t)blockIdx.y * Kt * 4096;
    const size_t bbase = (size_t)blockIdx.x * Kt * 4096;

    if (tid == 0) {
        for (int s = 0; s < NST; s++) { MBAR_INIT(mbF + 8 * s, 1); MBAR_INIT(mbE + 8 * s, 256); }
        FENCE_ASYNC();
    }
    __syncthreads();

    auto issue = [&](int slot, int c) {
        uint32_t d = sb + slot * STB;
        uint32_t bar = mbF + 8 * slot;
        MBAR_EXPECT(bar, (uint32_t)STB);
        BULK8K(d,        A  + abase + (size_t)c * 4096, bar);
        BULK8K(d + 8192, Bw + bbase + (size_t)c * 4096, bar);
    };
    if (tid == 0)
        for (int s = 0; s < NST; s++) issue(s, s);

    const int w = tid >> 5, lane = tid & 31;
    const int wm = w >> 2, wn = w & 3;
    const int g = lane >> 2, t = lane & 3;

    const int ra  = (lane & 7) + ((lane >> 3) & 1) * 8;
    const int sa  = lane >> 4;
    const int s3a = (ra >> 1) & 3;
    const int rb  = (lane & 7) + (lane >> 4) * 8;
    const int sbk = (lane >> 3) & 1;
    const int s3b = (rb >> 1) & 3;

    uint32_t aoff[2][4], boff[2][2];
    #pragma unroll
    for (int ks = 0; ks < 2; ks++) {
        #pragma unroll
        for (int mt = 0; mt < 4; mt++)
            aoff[ks][mt] = (uint32_t)((wm * 64 + mt * 16 + ra) * 64 + (((ks * 2 + sa) ^ s3a) * 16));
        #pragma unroll
        for (int np = 0; np < 2; np++)
            boff[ks][np] = (uint32_t)((wn * 32 + np * 16 + rb) * 64 + (((ks * 2 + sbk) ^ s3b) * 16));
    }

    float acc[4][4][4];
    #pragma unroll
    for (int i = 0; i < 4; i++)
        #pragma unroll
        for (int j = 0; j < 4; j++)
            #pragma unroll
            for (int e = 0; e < 4; e++) acc[i][j][e] = 0.f;

    int slot = 0, rph = 0;
    for (int c = 0; c < Kt; c++) {
        MBAR_WAIT(mbF + 8 * slot, rph);
        const uint32_t base = sb + slot * STB;
        #pragma unroll
        for (int ks = 0; ks < 2; ks++) {
            uint32_t a4[4][4], b4[2][4];
            #pragma unroll
            for (int mt = 0; mt < 4; mt++) LDSM4(a4[mt], base + aoff[ks][mt]);
            #pragma unroll
            for (int np = 0; np < 2; np++) LDSM4(b4[np], base + 8192 + boff[ks][np]);
            #pragma unroll
            for (int mt = 0; mt < 4; mt++)
                #pragma unroll
                for (int nt = 0; nt < 4; nt++)
                    mma_f16(acc[mt][nt], a4[mt], &b4[nt >> 1][(nt & 1) * 2]);
        }
        MBAR_ARRIVE(mbE + 8 * slot);
        if (tid == 0 && c + NST < Kt) {
            MBAR_WAIT(mbE + 8 * slot, rph);
            FENCE_ASYNC();
            issue(slot, c + NST);
        }
        if (++slot == NST) { slot = 0; rph ^= 1; }
    }

    const int row0 = blockIdx.y * 128, col0 = blockIdx.x * 128;
    #pragma unroll
    for (int mt = 0; mt < 4; mt++) {
        const int row = row0 + wm * 64 + mt * 16 + g;
        #pragma unroll
        for (int nt = 0; nt < 4; nt++) {
            const int col = col0 + wn * 32 + nt * 8 + 2 * t;
            const float* a = acc[mt][nt];
            const float b0v = bias ? bias[col] : 0.f;
            const float b1v = bias ? bias[col + 1] : 0.f;
            const float v0 = a[0] + b0v, v1 = a[1] + b1v;
            const float v2 = a[2] + b0v, v3 = a[3] + b1v;
            if (EPI == 0) {
                *(float2*)(C + (size_t)row * N + col)       = make_float2(v0, v1);
                *(float2*)(C + (size_t)(row + 8) * N + col) = make_float2(v2, v3);
            } else if (EPI == 1) {
                size_t o0 = tile_off(row, col, N), o1 = tile_off(row + 8, col, N);
                *(__half2*)(Cout + o0) = __floats2half2_rn(gelu_t(v0), gelu_t(v1));
                *(__half2*)(Cout + o1) = __floats2half2_rn(gelu_t(v2), gelu_t(v3));
            } else {
                const int bb = row >> 8;
                const float* gm = gmod + (size_t)bb * gstride;
                float2 x0 = *(float2*)(X + (size_t)row * N + col);
                float2 x1 = *(float2*)(X + (size_t)(row + 8) * N + col);
                x0.x += gm[col] * v0;  x0.y += gm[col + 1] * v1;
                x1.x += gm[col] * v2;  x1.y += gm[col + 1] * v3;
                *(float2*)(X + (size_t)row * N + col)       = x0;
                *(float2*)(X + (size_t)(row + 8) * N + col) = x1;
            }
        }
    }
}

// W[K,N] f32 -> tile-major swizzled fp16 of Wt[N,K]
__global__ __launch_bounds__(256) void wprep(const float* __restrict__ W,
    __half* __restrict__ Wh, int K, int N) {
    __shared__ float s[32 * 128];
    const int i = blockIdx.x, j = blockIdx.y;
    #pragma unroll
    for (int e = 0; e < 16; e++) {
        int idx = threadIdx.x + e * 256;
        int kk = idx >> 7, r = idx & 127;
        s[kk * 128 + r] = W[(size_t)(j * 32 + kk) * N + i * 128 + r];
    }
    __syncthreads();
    const size_t tbase = ((size_t)i * (K >> 5) + j) * 4096;
    #pragma unroll
    for (int e = 0; e < 2; e++) {
        int q = threadIdx.x * 2 + e;
        int r = q >> 2, cp = q & 3;
        int c = cp ^ ((r >> 1) & 3);
        uint32_t hw[4];
        #pragma unroll
        for (int u = 0; u < 4; u++) {
            __half2 hp = __floats2half2_rn(s[(c * 8 + 2 * u) * 128 + r],
                                           s[(c * 8 + 2 * u + 1) * 128 + r]);
            hw[u] = *(uint32_t*)&hp;
        }
        *(uint4*)(Wh + tbase + r * 32 + cp * 8) = make_uint4(hw[0], hw[1], hw[2], hw[3]);
    }
}

// fp32 [M,1024] row-major -> tile-major fp16
__global__ void split_tile(const float* __restrict__ s, __half* __restrict__ hi) {
    int idx = blockIdx.x * 256 + threadIdx.x;
    int row = idx >> 10, d = idx & 1023;
    hi[tile_off(row, d, Dc)] = __float2half(s[idx]);
}

__global__ void copy_kernel(const float* __restrict__ src, float* __restrict__ dst, int n) {
    int i = blockIdx.x * blockDim.x + threadIdx.x;
    if (i < n) dst[i] = src[i];
}
__global__ void silu_kernel(const float* __restrict__ c, float* __restrict__ out, int n) {
    int i = blockIdx.x * blockDim.x + threadIdx.x;
    if (i < n) { float x = c[i]; out[i] = x / (1.f + expf(-x)); }
}
__device__ __forceinline__ float block_reduce_sum(float v, float* red) {
    int tid = threadIdx.x;
    red[tid] = v;
    __syncthreads();
    #pragma unroll
    for (int s = 128; s > 0; s >>= 1) {
        if (tid < s) red[tid] += red[tid + s];
        __syncthreads();
    }
    float r = red[0];
    __syncthreads();
    return r;
}

__global__ void ln_mod(const float* __restrict__ x, const float* __restrict__ ada,
                       int off_shift, int off_scale, __half* __restrict__ hi) {
    __shared__ float red[256];
    int row = blockIdx.x, b = row / Tc, tid = threadIdx.x;
    const float* xr = x + (size_t)row * Dc;
    float v[4], s = 0.f;
    #pragma unroll
    for (int i = 0; i < 4; i++) { v[i] = xr[tid + i * 256]; s += v[i]; }
    float mean = block_reduce_sum(s, red) * (1.f / 1024.f);
    float sq = 0.f;
    #pragma unroll
    for (int i = 0; i < 4; i++) { float d = v[i] - mean; sq += d * d; }
    float rstd = rsqrtf(block_reduce_sum(sq, red) * (1.f / 1024.f) + 1e-5f);
    const float* ab = ada + (size_t)b * 6 * Dc;
    #pragma unroll
    for (int i = 0; i < 4; i++) {
        int d = tid + i * 256;
        float o = (v[i] - mean) * rstd * (1.f + ab[off_scale + d]) + ab[off_shift + d];
        hi[tile_off(row, d, Dc)] = __float2half(o);
    }
}

__global__ void rmsrope_kernel(float* __restrict__ t, const float* __restrict__ w,
                               int S, float cmul, const float* __restrict__ gate) {
    int warp = (blockIdx.x * blockDim.x + threadIdx.x) >> 5;
    int lane = threadIdx.x & 31;
    int s = (warp / Hc) % S;
    float* p = t + (size_t)warp * HDc;
    float x0 = p[lane], x1 = p[lane + 32];
    float ss = x0 * x0 + x1 * x1;
    #pragma unroll
    for (int o = 16; o; o >>= 1) ss += __shfl_xor_sync(0xffffffffu, ss, o);
    float inv = rsqrtf(ss * (1.f / 64.f) + 1e-6f);
    x0 = x0 * inv * w[lane];
    x1 = x1 * inv * w[lane + 32];
    float fr = (float)s * expf(-(float)lane * 0.28782313662425575f);
    float c = cosf(fr), sn = sinf(fr);
    float mult = cmul;
    if (gate) mult *= 1.f / (1.f + expf(-gate[0]));
    p[lane]      = (x0 * c - x1 * sn) * mult;
    p[lane + 32] = (x1 * c + x0 * sn) * mult;
}

__global__ void small_gemm_kernel(const float* __restrict__ A, const float* __restrict__ W,
                                  const float* __restrict__ bias, float* __restrict__ C,
                                  int Nn, int Kk) {
    int n = blockIdx.x * blockDim.x + threadIdx.x;
    int b = blockIdx.y;
    if (n >= Nn) return;
    const float* a = A + (size_t)b * Kk;
    float acc = 0.f;
    #pragma unroll 4
    for (int k = 0; k < Kk; k++) acc += a[k] * W[(size_t)k * Nn + n];
    C[(size_t)b * Nn + n] = acc + (bias ? bias[n] : 0.f);
}

// flash attention fp32, output tile-major fp16
__global__ __launch_bounds__(128) void flash_kernel(
    const float* __restrict__ q,
    const float* __restrict__ ks, const float* __restrict__ vs,
    const float* __restrict__ ka, const float* __restrict__ va,
    const float* __restrict__ kt, const float* __restrict__ vt,
    __half* __restrict__ oh)
{
    __shared__ float4 Ks4[32][16];
    __shared__ float4 Vs4[32][16];
    int tid = threadIdx.x, bh = blockIdx.y;
    int b = bh / Hc, h = bh % Hc;
    int qi = blockIdx.x * 128 + tid;

    float qr[64], oa[64];
    const float* qp = q + (size_t)(b * Tc + qi) * Dc + h * HDc;
    #pragma unroll
    for (int j = 0; j < 16; j++) {
        float4 v4 = *(const float4*)&qp[j * 4];
        qr[4*j] = v4.x; qr[4*j+1] = v4.y; qr[4*j+2] = v4.z; qr[4*j+3] = v4.w;
    }
    #pragma unroll
    for (int d = 0; d < 64; d++) oa[d] = 0.f;
    float m = -1e30f, l = 0.f;

    const float* Kseg[3] = {ks, ka, kt};
    const float* Vseg[3] = {vs, va, vt};
    const int Slen[3] = {Tc, SAc, STc};

    #pragma unroll
    for (int seg = 0; seg < 3; seg++) {
        const float* K = Kseg[seg];
        const float* V = Vseg[seg];
        int S = Slen[seg];
        for (int s0 = 0; s0 < S; s0 += 32) {
            __syncthreads();
            #pragma unroll
            for (int i = 0; i < 4; i++) {
                int idx = tid + i * 128;
                int r = idx >> 4, cc = idx & 15;
                size_t base = (size_t)(b * S + s0 + r) * Dc + h * HDc + cc * 4;
                Ks4[r][cc] = *(const float4*)&K[base];
                Vs4[r][cc] = *(const float4*)&V[base];
            }
            __syncthreads();
            float sc[32], tmax = -1e30f;
            #pragma unroll
            for (int s = 0; s < 32; s++) {
                float d0 = 0.f, d1 = 0.f, d2 = 0.f, d3 = 0.f;
                #pragma unroll
                for (int j = 0; j < 16; j++) {
                    float4 kv = Ks4[s][j];
                    d0 = fmaf(qr[4*j],   kv.x, d0);
                    d1 = fmaf(qr[4*j+1], kv.y, d1);
                    d2 = fmaf(qr[4*j+2], kv.z, d2);
                    d3 = fmaf(qr[4*j+3], kv.w, d3);
                }
                sc[s] = (d0 + d1) + (d2 + d3);
                tmax = fmaxf(tmax, sc[s]);
            }
            float mnew = fmaxf(m, tmax);
            float corr = __expf(m - mnew);
            l *= corr;
            #pragma unroll
            for (int d = 0; d < 64; d++) oa[d] *= corr;
            #pragma unroll
            for (int s = 0; s < 32; s++) {
                float p = __expf(sc[s] - mnew);
                l += p;
                #pragma unroll
                for (int j = 0; j < 16; j++) {
                    float4 vv = Vs4[s][j];
                    oa[4*j]   = fmaf(p, vv.x, oa[4*j]);
                    oa[4*j+1] = fmaf(p, vv.y, oa[4*j+1]);
                    oa[4*j+2] = fmaf(p, vv.z, oa[4*j+2]);
                    oa[4*j+3] = fmaf(p, vv.w, oa[4*j+3]);
                }
            }
            m = mnew;
        }
    }
    float invl = 1.f / l;
    int orow = b * Tc + qi;
    #pragma unroll
    for (int d = 0; d < 64; d++)
        oh[tile_off(orow, h * HDc + d, Dc)] = __float2half(oa[d] * invl);
}

__global__ void final_kernel(const float* __restrict__ x, const float* __restrict__ lw,
                             const float* __restrict__ lb, const float* __restrict__ Wout,
                             const float* __restrict__ bout, float* __restrict__ out) {
    __shared__ float red[256];
    int row = blockIdx.x, tid = threadIdx.x;
    const float* xr = x + (size_t)row * Dc;
    float v[4], s = 0.f;
    #pragma unroll
    for (int i = 0; i < 4; i++) { v[i] = xr[tid + i * 256]; s += v[i]; }
    float mean = block_reduce_sum(s, red) * (1.f / 1024.f);
    float sq = 0.f;
    #pragma unroll
    for (int i = 0; i < 4; i++) { float d = v[i] - mean; sq += d * d; }
    float rstd = rsqrtf(block_reduce_sum(sq, red) * (1.f / 1024.f) + 1e-5f);
    float p0 = 0.f, p1 = 0.f, p2 = 0.f;
    #pragma unroll
    for (int i = 0; i < 4; i++) {
        int d = tid + i * 256;
        float y = (v[i] - mean) * rstd * lw[d] + lb[d];
        p0 = fmaf(y, Wout[d * OUTc + 0], p0);
        p1 = fmaf(y, Wout[d * OUTc + 1], p1);
        p2 = fmaf(y, Wout[d * OUTc + 2], p2);
    }
    p0 = block_reduce_sum(p0, red);
    p1 = block_reduce_sum(p1, red);
    p2 = block_reduce_sum(p2, red);
    if (tid == 0) {
        out[row * OUTc + 0] = p0 + bout[0];
        out[row * OUTc + 1] = p1 + bout[1];
        out[row * OUTc + 2] = p2 + bout[2];
    }
}

extern "C" void kernel_launch(void* const* d_in, const int* in_sizes, int n_in,
                              void* d_out, int out_size)
{
    (void)in_sizes; (void)n_in; (void)out_size;
    const float* x    = (const float*)d_in[0];
    const float* cond = (const float*)d_in[1];
    const float* adp  = (const float*)d_in[2];
    const float* task = (const float*)d_in[3];
    const float* Wq   = (const float*)d_in[4];
    const float* bq   = (const float*)d_in[5];
    const float* Wks  = (const float*)d_in[6];
    const float* Wvs  = (const float*)d_in[7];
    const float* Wka  = (const float*)d_in[8];
    const float* Wva  = (const float*)d_in[9];
    const float* Wkt  = (const float*)d_in[10];
    const float* Wvt  = (const float*)d_in[11];
    const float* Wo   = (const float*)d_in[12];
    const float* bo   = (const float*)d_in[13];
    const float* qnw  = (const float*)d_in[14];
    const float* knw  = (const float*)d_in[15];
    const float* gate = (const float*)d_in[16];
    const float* Wada = (const float*)d_in[17];
    const float* bada = (const float*)d_in[18];
    const float* W1   = (const float*)d_in[19];
    const float* b1   = (const float*)d_in[20];
    const float* W2   = (const float*)d_in[21];
    const float* b2   = (const float*)d_in[22];
    const float* lnfw = (const float*)d_in[23];
    const float* lnfb = (const float*)d_in[24];
    const float* Wout = (const float*)d_in[25];
    const float* bout = (const float*)d_in[26];
    float* out = (float*)d_out;

    cudaFuncSetAttribute(mma_gemm<0>, cudaFuncAttributeMaxDynamicSharedMemorySize, GSMEM);
    cudaFuncSetAttribute(mma_gemm<1>, cudaFuncAttributeMaxDynamicSharedMemorySize, GSMEM);
    cudaFuncSetAttribute(mma_gemm<2>, cudaFuncAttributeMaxDynamicSharedMemorySize, GSMEM);

    float *px, *pq, *pks, *pvs, *pka, *pva, *pkt, *pvt, *pada, *psc;
    __half *ph, *po, *pf, *pa, *pt, *pw;
    cudaGetSymbolAddress((void**)&px,  g_x);
    cudaGetSymbolAddress((void**)&pq,  g_q);
    cudaGetSymbolAddress((void**)&pks, g_ks);
    cudaGetSymbolAddress((void**)&pvs, g_vs);
    cudaGetSymbolAddress((void**)&pka, g_ka);
    cudaGetSymbolAddress((void**)&pva, g_va);
    cudaGetSymbolAddress((void**)&pkt, g_kt);
    cudaGetSymbolAddress((void**)&pvt, g_vt);
    cudaGetSymbolAddress((void**)&pada, g_ada);
    cudaGetSymbolAddress((void**)&psc,  g_sc);
    cudaGetSymbolAddress((void**)&ph, g_h);
    cudaGetSymbolAddress((void**)&po, g_o);
    cudaGetSymbolAddress((void**)&pf, g_ff);
    cudaGetSymbolAddress((void**)&pa, g_adp);
    cudaGetSymbolAddress((void**)&pt, g_tsk);
    cudaGetSymbolAddress((void**)&pw, g_w);

    copy_kernel<<<(MTc*Dc)/256, 256>>>(x, px, MTc*Dc);
    silu_kernel<<<(Bc*Dc)/256, 256>>>(cond, psc, Bc*Dc);
    split_tile<<<(MAc*Dc)/256, 256>>>(adp,  pa);
    split_tile<<<(MSc*Dc)/256, 256>>>(task, pt);

    const float* wsrc[8] = {Wq, Wks, Wvs, Wka, Wva, Wkt, Wvt, Wo};
    for (int i = 0; i < Lc; i++) {
        size_t base = (size_t)i * WPLc;
        for (int mtx = 0; mtx < 8; mtx++)
            wprep<<<dim3(Dc/128, Dc/32), 256>>>(
                wsrc[mtx] + (size_t)i * DDc, pw + base + (size_t)mtx * DDc, Dc, Dc);
        wprep<<<dim3(DFFc/128, Dc/32), 256>>>(
            W1 + (size_t)i * Dc * DFFc, pw + base + 8*DDc, Dc, DFFc);
        wprep<<<dim3(Dc/128, DFFc/32), 256>>>(
            W2 + (size_t)i * DFFc * Dc, pw + base + 8*DDc + (size_t)Dc*DFFc, DFFc, Dc);
    }

    for (int i = 0; i < Lc; i++) {
        size_t wb = (size_t)i * WPLc;
        __half *wv[8];
        for (int m = 0; m < 8; m++) wv[m] = pw + wb + (size_t)m*DDc;
        __half* w1 = pw + wb + 8*(size_t)DDc;
        __half* w2 = pw + wb + 8*(size_t)DDc + (size_t)Dc*DFFc;

        small_gemm_kernel<<<dim3((6*Dc)/256, Bc), 256>>>(
            psc, Wada + (size_t)i*Dc*6*Dc, bada + (size_t)i*6*Dc, pada, 6*Dc, Dc);

        ln_mod<<<MTc, 256>>>(px, pada, 0, Dc, ph);

        mma_gemm<0><<<dim3(Dc/128, MTc/128), 256, GSMEM>>>(ph, wv[0], bq + (size_t)i*Dc, pq,  MTc, Dc, Dc, nullptr, 0, nullptr, nullptr);
        mma_gemm<0><<<dim3(Dc/128, MTc/128), 256, GSMEM>>>(ph, wv[1], nullptr, pks, MTc, Dc, Dc, nullptr, 0, nullptr, nullptr);
        mma_gemm<0><<<dim3(Dc/128, MTc/128), 256, GSMEM>>>(ph, wv[2], nullptr, pvs, MTc, Dc, Dc, nullptr, 0, nullptr, nullptr);
        mma_gemm<0><<<dim3(Dc/128, MAc/128), 256, GSMEM>>>(pa, wv[3], nullptr, pka, MAc, Dc, Dc, nullptr, 0, nullptr, nullptr);
        mma_gemm<0><<<dim3(Dc/128, MAc/128), 256, GSMEM>>>(pa, wv[4], nullptr, pva, MAc, Dc, Dc, nullptr, 0, nullptr, nullptr);
        mma_gemm<0><<<dim3(Dc/128, MSc/128), 256, GSMEM>>>(pt, wv[5], nullptr, pkt, MSc, Dc, Dc, nullptr, 0, nullptr, nullptr);
        mma_gemm<0><<<dim3(Dc/128, MSc/128), 256, GSMEM>>>(pt, wv[6], nullptr, pvt, MSc, Dc, Dc, nullptr, 0, nullptr, nullptr);

        rmsrope_kernel<<<(MTc*Hc*32)/256, 256>>>(pq,  qnw + (size_t)i*HDc, Tc,  0.125f, nullptr);
        rmsrope_kernel<<<(MTc*Hc*32)/256, 256>>>(pks, knw + (size_t)i*HDc, Tc,  1.f,    nullptr);
        rmsrope_kernel<<<(MAc*Hc*32)/256, 256>>>(pka, knw + (size_t)i*HDc, SAc, 1.f,    nullptr);
        rmsrope_kernel<<<(MSc*Hc*32)/256, 256>>>(pkt, knw + (size_t)i*HDc, STc, 1.f,    gate + i);

        flash_kernel<<<dim3(Tc/128, Bc*Hc), 128>>>(pq, pks, pvs, pka, pva, pkt, pvt, po);

        mma_gemm<2><<<dim3(Dc/128, MTc/128), 256, GSMEM>>>(po, wv[7], bo + (size_t)i*Dc, nullptr,
                                                           MTc, Dc, Dc, pada + 2*Dc, 6*Dc, px, nullptr);

        ln_mod<<<MTc, 256>>>(px, pada, 3*Dc, 4*Dc, ph);

        mma_gemm<1><<<dim3(DFFc/128, MTc/128), 256, GSMEM>>>(ph, w1, b1 + (size_t)i*DFFc, nullptr,
                                                             MTc, DFFc, Dc, nullptr, 0, nullptr, pf);

        mma_gemm<2><<<dim3(Dc/128, MTc/128), 256, GSMEM>>>(pf, w2, b2 + (size_t)i*Dc, nullptr,
                                                           MTc, Dc, DFFc, pada + 5*Dc, 6*Dc, px, nullptr);
    }

    final_kernel<<<MTc, 256>>>(px, lnfw, lnfb, Wout, bout, out);
}

// round 10
// speedup vs baseline: 3.1353x; 1.8460x over previous
#include <cuda_runtime.h>
#include <cuda_fp16.h>
#include <math.h>
#include <stdint.h>

#define Lc 6
#define Bc 32
#define Tc 256
#define SAc 512
#define STc 128
#define Dc 1024
#define Hc 16
#define HDc 64
#define DFFc 4096
#define OUTc 3
#define MTc (Bc*Tc)
#define MAc (Bc*SAc)
#define MSc (Bc*STc)
#define DDc (Dc*Dc)
#define WPLc (8*DDc + Dc*DFFc + DFFc*Dc)
#define QSz (Bc*Hc*Tc*HDc)
#define ASz (Bc*Hc*SAc*HDc)
#define TSz (Bc*Hc*STc*HDc)

__device__ float g_x[MTc*Dc];
__device__ float g_q[MTc*Dc];
__device__ float g_ks[MTc*Dc];
__device__ float g_ka[MAc*Dc];
__device__ float g_kt[MSc*Dc];
__device__ float g_ada[Bc*6*Dc];
__device__ float g_sc[Bc*Dc];

__device__ __align__(256) __half g_h[MTc*Dc];
__device__ __align__(256) __half g_o[MTc*Dc];
__device__ __align__(256) __half g_ff[MTc*DFFc];
__device__ __align__(256) __half g_adp[MAc*Dc];
__device__ __align__(256) __half g_tsk[MSc*Dc];
__device__ __align__(256) __half g_w[Lc*WPLc];
__device__ __align__(256) __half g_qh[QSz], g_ksh[QSz], g_vsh[QSz];
__device__ __align__(256) __half g_kah[ASz], g_vah[ASz];
__device__ __align__(256) __half g_kth[TSz], g_vth[TSz];

__device__ __forceinline__ uint32_t smem_u32(const void* p) {
    uint32_t a;
    asm("{ .reg .u64 t; cvta.to.shared.u64 t, %1; cvt.u32.u64 %0, t; }" : "=r"(a) : "l"(p));
    return a;
}
#define MBAR_INIT(a, n) asm volatile("mbarrier.init.shared.b64 [%0], %1;" :: "r"(a), "r"(n) : "memory")
#define MBAR_EXPECT(a, tx) asm volatile("mbarrier.arrive.expect_tx.shared.b64 _, [%0], %1;" :: "r"(a), "r"(tx) : "memory")
#define MBAR_ARRIVE(a) asm volatile("mbarrier.arrive.shared.b64 _, [%0];" :: "r"(a) : "memory")
#define MBAR_WAIT(a, ph) do { \
    uint32_t _m = (a), _p = (ph), _d; \
    asm volatile("{ .reg .pred p; mbarrier.try_wait.parity.acquire.cta.shared::cta.b64 p, [%1], %2; selp.b32 %0,1,0,p; }" \
        : "=r"(_d) : "r"(_m), "r"(_p) : "memory"); \
    if (!_d) { \
        asm volatile("{ .reg .pred P1; WL_%=: mbarrier.try_wait.parity.acquire.cta.shared::cta.b64 P1, [%0], %1, 0x989680; @P1 bra.uni WD_%=; bra.uni WL_%=; WD_%=: }" \
            :: "r"(_m), "r"(_p) : "memory"); \
    } } while (0)
#define BULK8K(dst, src, bar) asm volatile( \
    "cp.async.bulk.shared::cluster.global.mbarrier::complete_tx::bytes [%0], [%1], 8192, [%2];" \
    :: "r"(dst), "l"(src), "r"(bar) : "memory")
#define FENCE_ASYNC() asm volatile("fence.proxy.async.shared::cta;" ::: "memory")
#define LDSM4(r, a) asm volatile( \
    "ldmatrix.sync.aligned.m8n8.x4.shared.b16 {%0,%1,%2,%3}, [%4];" \
    : "=r"((r)[0]), "=r"((r)[1]), "=r"((r)[2]), "=r"((r)[3]) : "r"(a))
#define LDSM4T(r, a) asm volatile( \
    "ldmatrix.sync.aligned.m8n8.x4.trans.shared.b16 {%0,%1,%2,%3}, [%4];" \
    : "=r"((r)[0]), "=r"((r)[1]), "=r"((r)[2]), "=r"((r)[3]) : "r"(a))

__device__ __forceinline__ void mma_f16(float* c, const uint32_t* a, const uint32_t* b) {
    asm volatile(
        "mma.sync.aligned.m16n8k16.row.col.f32.f16.f16.f32 "
        "{%0,%1,%2,%3}, {%4,%5,%6,%7}, {%8,%9}, {%0,%1,%2,%3};"
        : "+f"(c[0]), "+f"(c[1]), "+f"(c[2]), "+f"(c[3])
        : "r"(a[0]), "r"(a[1]), "r"(a[2]), "r"(a[3]), "r"(b[0]), "r"(b[1]));
}
__device__ __forceinline__ float gelu_t(float c) {
    float t = 0.7978845608028654f * (c + 0.044715f * c * c * c);
    return 0.5f * c * (1.f + tanhf(t));
}
// (row,col) of [M,Ncols] -> tile-major swizzled element offset (128x32 tiles, 8KB)
__device__ __forceinline__ size_t tile_off(int row, int col, int Ncols) {
    int r = row & 127;
    int cp = ((col >> 3) & 3) ^ ((r >> 1) & 3);
    return ((size_t)(row >> 7) * (Ncols >> 5) + (col >> 5)) * 4096 + r * 32 + cp * 8 + (col & 7);
}

// ---- fp16 single-pass MMA GEMM, 8-stage bulk ring ----
// EPI 0: C=acc+bias f32 | EPI 1: gelu->fp16 tile-major | EPI 2: X += gmod*(acc+bias)
// EPI 3: fp16 per-(b,h) tile-major [S][64]  (for V projections)
#define NST 8
#define STB 16384
#define GSMEM (NST*STB + 128)
template <int EPI>
__global__ __launch_bounds__(256) void mma_gemm(
    const __half* __restrict__ A, const __half* __restrict__ Bw,
    const float* __restrict__ bias, float* __restrict__ C, int M, int N, int K,
    const float* __restrict__ gmod, int gstride, float* __restrict__ X,
    __half* __restrict__ Cout, int sshift)
{
    extern __shared__ __align__(128) char smem[];
    const int tid = threadIdx.x;
    const uint32_t sb = smem_u32(smem);
    const uint32_t mbF = sb + NST * STB;
    const uint32_t mbE = mbF + 8 * NST;
    const int Kt = K >> 5;
    const size_t abase = (size_t)blockIdx.y * Kt * 4096;
    const size_t bbase = (size_t)blockIdx.x * Kt * 4096;

    if (tid == 0) {
        for (int s = 0; s < NST; s++) { MBAR_INIT(mbF + 8 * s, 1); MBAR_INIT(mbE + 8 * s, 256); }
        FENCE_ASYNC();
    }
    __syncthreads();

    auto issue = [&](int slot, int c) {
        uint32_t d = sb + slot * STB;
        uint32_t bar = mbF + 8 * slot;
        MBAR_EXPECT(bar, (uint32_t)STB);
        BULK8K(d,        A  + abase + (size_t)c * 4096, bar);
        BULK8K(d + 8192, Bw + bbase + (size_t)c * 4096, bar);
    };
    if (tid == 0)
        for (int s = 0; s < NST; s++) issue(s, s);

    const int w = tid >> 5, lane = tid & 31;
    const int wm = w >> 2, wn = w & 3;
    const int g = lane >> 2, t = lane & 3;

    const int ra  = (lane & 7) + ((lane >> 3) & 1) * 8;
    const int sa  = lane >> 4;
    const int s3a = (ra >> 1) & 3;
    const int rb  = (lane & 7) + (lane >> 4) * 8;
    const int sbk = (lane >> 3) & 1;
    const int s3b = (rb >> 1) & 3;

    uint32_t aoff[2][4], boff[2][2];
    #pragma unroll
    for (int ks = 0; ks < 2; ks++) {
        #pragma unroll
        for (int mt = 0; mt < 4; mt++)
            aoff[ks][mt] = (uint32_t)((wm * 64 + mt * 16 + ra) * 64 + (((ks * 2 + sa) ^ s3a) * 16));
        #pragma unroll
        for (int np = 0; np < 2; np++)
            boff[ks][np] = (uint32_t)((wn * 32 + np * 16 + rb) * 64 + (((ks * 2 + sbk) ^ s3b) * 16));
    }

    float acc[4][4][4];
    #pragma unroll
    for (int i = 0; i < 4; i++)
        #pragma unroll
        for (int j = 0; j < 4; j++)
            #pragma unroll
            for (int e = 0; e < 4; e++) acc[i][j][e] = 0.f;

    int slot = 0, rph = 0;
    for (int c = 0; c < Kt; c++) {
        MBAR_WAIT(mbF + 8 * slot, rph);
        const uint32_t base = sb + slot * STB;
        #pragma unroll
        for (int ks = 0; ks < 2; ks++) {
            uint32_t a4[4][4], b4[2][4];
            #pragma unroll
            for (int mt = 0; mt < 4; mt++) LDSM4(a4[mt], base + aoff[ks][mt]);
            #pragma unroll
            for (int np = 0; np < 2; np++) LDSM4(b4[np], base + 8192 + boff[ks][np]);
            #pragma unroll
            for (int mt = 0; mt < 4; mt++)
                #pragma unroll
                for (int nt = 0; nt < 4; nt++)
                    mma_f16(acc[mt][nt], a4[mt], &b4[nt >> 1][(nt & 1) * 2]);
        }
        MBAR_ARRIVE(mbE + 8 * slot);
        if (tid == 0 && c + NST < Kt) {
            MBAR_WAIT(mbE + 8 * slot, rph);
            FENCE_ASYNC();
            issue(slot, c + NST);
        }
        if (++slot == NST) { slot = 0; rph ^= 1; }
    }

    const int row0 = blockIdx.y * 128, col0 = blockIdx.x * 128;
    #pragma unroll
    for (int mt = 0; mt < 4; mt++) {
        const int row = row0 + wm * 64 + mt * 16 + g;
        #pragma unroll
        for (int nt = 0; nt < 4; nt++) {
            const int col = col0 + wn * 32 + nt * 8 + 2 * t;
            const float* a = acc[mt][nt];
            const float b0v = bias ? bias[col] : 0.f;
            const float b1v = bias ? bias[col + 1] : 0.f;
            const float v0 = a[0] + b0v, v1 = a[1] + b1v;
            const float v2 = a[2] + b0v, v3 = a[3] + b1v;
            if (EPI == 0) {
                *(float2*)(C + (size_t)row * N + col)       = make_float2(v0, v1);
                *(float2*)(C + (size_t)(row + 8) * N + col) = make_float2(v2, v3);
            } else if (EPI == 1) {
                size_t o0 = tile_off(row, col, N), o1 = tile_off(row + 8, col, N);
                *(__half2*)(Cout + o0) = __floats2half2_rn(gelu_t(v0), gelu_t(v1));
                *(__half2*)(Cout + o1) = __floats2half2_rn(gelu_t(v2), gelu_t(v3));
            } else if (EPI == 3) {
                const int Sm = (1 << sshift) - 1;
                const int h = col >> 6, d = col & 63;
                size_t base0 = (((size_t)(row >> sshift) * Hc + h) << sshift) * 64;
                *(__half2*)(Cout + base0 + tile_off(row & Sm, d, 64)) = __floats2half2_rn(v0, v1);
                *(__half2*)(Cout + base0 + tile_off((row + 8) & Sm, d, 64)) = __floats2half2_rn(v2, v3);
            } else {
                const int bb = row >> 8;
                const float* gm = gmod + (size_t)bb * gstride;
                float2 x0 = *(float2*)(X + (size_t)row * N + col);
                float2 x1 = *(float2*)(X + (size_t)(row + 8) * N + col);
                x0.x += gm[col] * v0;  x0.y += gm[col + 1] * v1;
                x1.x += gm[col] * v2;  x1.y += gm[col + 1] * v3;
                *(float2*)(X + (size_t)row * N + col)       = x0;
                *(float2*)(X + (size_t)(row + 8) * N + col) = x1;
            }
        }
    }
}

// W[K,N] f32 -> tile-major swizzled fp16 of Wt[N,K]
__global__ __launch_bounds__(256) void wprep(const float* __restrict__ W,
    __half* __restrict__ Wh, int K, int N) {
    __shared__ float s[32 * 128];
    const int i = blockIdx.x, j = blockIdx.y;
    #pragma unroll
    for (int e = 0; e < 16; e++) {
        int idx = threadIdx.x + e * 256;
        int kk = idx >> 7, r = idx & 127;
        s[kk * 128 + r] = W[(size_t)(j * 32 + kk) * N + i * 128 + r];
    }
    __syncthreads();
    const size_t tbase = ((size_t)i * (K >> 5) + j) * 4096;
    #pragma unroll
    for (int e = 0; e < 2; e++) {
        int q = threadIdx.x * 2 + e;
        int r = q >> 2, cp = q & 3;
        int c = cp ^ ((r >> 1) & 3);
        uint32_t hw[4];
        #pragma unroll
        for (int u = 0; u < 4; u++) {
            __half2 hp = __floats2half2_rn(s[(c * 8 + 2 * u) * 128 + r],
                                           s[(c * 8 + 2 * u + 1) * 128 + r]);
            hw[u] = *(uint32_t*)&hp;
        }
        *(uint4*)(Wh + tbase + r * 32 + cp * 8) = make_uint4(hw[0], hw[1], hw[2], hw[3]);
    }
}

// fp32 [M,1024] row-major -> tile-major fp16
__global__ void split_tile(const float* __restrict__ s, __half* __restrict__ hi) {
    int idx = blockIdx.x * 256 + threadIdx.x;
    int row = idx >> 10, d = idx & 1023;
    hi[tile_off(row, d, Dc)] = __float2half(s[idx]);
}

__global__ void copy_kernel(const float* __restrict__ src, float* __restrict__ dst, int n) {
    int i = blockIdx.x * blockDim.x + threadIdx.x;
    if (i < n) dst[i] = src[i];
}
__global__ void silu_kernel(const float* __restrict__ c, float* __restrict__ out, int n) {
    int i = blockIdx.x * blockDim.x + threadIdx.x;
    if (i < n) { float x = c[i]; out[i] = x / (1.f + expf(-x)); }
}
__device__ __forceinline__ float block_reduce_sum(float v, float* red) {
    int tid = threadIdx.x;
    red[tid] = v;
    __syncthreads();
    #pragma unroll
    for (int s = 128; s > 0; s >>= 1) {
        if (tid < s) red[tid] += red[tid + s];
        __syncthreads();
    }
    float r = red[0];
    __syncthreads();
    return r;
}

__global__ void ln_mod(const float* __restrict__ x, const float* __restrict__ ada,
                       int off_shift, int off_scale, __half* __restrict__ hi) {
    __shared__ float red[256];
    int row = blockIdx.x, b = row / Tc, tid = threadIdx.x;
    const float* xr = x + (size_t)row * Dc;
    float v[4], s = 0.f;
    #pragma unroll
    for (int i = 0; i < 4; i++) { v[i] = xr[tid + i * 256]; s += v[i]; }
    float mean = block_reduce_sum(s, red) * (1.f / 1024.f);
    float sq = 0.f;
    #pragma unroll
    for (int i = 0; i < 4; i++) { float d = v[i] - mean; sq += d * d; }
    float rstd = rsqrtf(block_reduce_sum(sq, red) * (1.f / 1024.f) + 1e-5f);
    const float* ab = ada + (size_t)b * 6 * Dc;
    #pragma unroll
    for (int i = 0; i < 4; i++) {
        int d = tid + i * 256;
        float o = (v[i] - mean) * rstd * (1.f + ab[off_scale + d]) + ab[off_shift + d];
        hi[tile_off(row, d, Dc)] = __float2half(o);
    }
}

// RMSNorm + RoPE on fp32 GEMM out [b*S+s][h*64+d]; write fp16 per-(b,h) tile-major [S][64]
__global__ void rmsrope_h(const float* __restrict__ in, const float* __restrict__ w,
                          int sLog, float cmul, const float* __restrict__ gate,
                          __half* __restrict__ outh) {
    int warp = (blockIdx.x * blockDim.x + threadIdx.x) >> 5;
    int lane = threadIdx.x & 31;
    int h = warp & 15;
    int s = (warp >> 4) & ((1 << sLog) - 1);
    int b = warp >> (4 + sLog);
    const float* p = in + (size_t)warp * HDc;
    float x0 = p[lane], x1 = p[lane + 32];
    float ss = x0 * x0 + x1 * x1;
    #pragma unroll
    for (int o = 16; o; o >>= 1) ss += __shfl_xor_sync(0xffffffffu, ss, o);
    float inv = rsqrtf(ss * (1.f / 64.f) + 1e-6f);
    x0 = x0 * inv * w[lane];
    x1 = x1 * inv * w[lane + 32];
    float fr = (float)s * expf(-(float)lane * 0.28782313662425575f);
    float c = cosf(fr), sn = sinf(fr);
    float mult = cmul;
    if (gate) mult *= 1.f / (1.f + expf(-gate[0]));
    size_t base = (((size_t)(b * Hc + h)) << sLog) * 64;
    outh[base + tile_off(s, lane, 64)]      = __float2half((x0 * c - x1 * sn) * mult);
    outh[base + tile_off(s, lane + 32, 64)] = __float2half((x1 * c + x0 * sn) * mult);
}

__global__ void small_gemm_kernel(const float* __restrict__ A, const float* __restrict__ W,
                                  const float* __restrict__ bias, float* __restrict__ C,
                                  int Nn, int Kk) {
    int n = blockIdx.x * blockDim.x + threadIdx.x;
    int b = blockIdx.y;
    if (n >= Nn) return;
    const float* a = A + (size_t)b * Kk;
    float acc = 0.f;
    #pragma unroll 4
    for (int k = 0; k < Kk; k++) acc += a[k] * W[(size_t)k * Nn + n];
    C[(size_t)b * Nn + n] = acc + (bias ? bias[n] : 0.f);
}

// ---- fp16 tensor-core flash attention ----
// grid (T/128, B*H), 256 threads; warp w handles q rows 16w..16w+15. 7 kv blocks of 128.
#define FSMEM (16384 + 2*32768 + 64)
__global__ __launch_bounds__(256) void flash_mma(
    const __half* __restrict__ qh,
    const __half* __restrict__ ksh, const __half* __restrict__ vsh,
    const __half* __restrict__ kah, const __half* __restrict__ vah,
    const __half* __restrict__ kth, const __half* __restrict__ vth,
    __half* __restrict__ oh)
{
    extern __shared__ __align__(128) char smem[];
    const int tid = threadIdx.x, w = tid >> 5, lane = tid & 31;
    const int g = lane >> 2, t = lane & 3;
    const int bh = blockIdx.y, b = bh >> 4, h = bh & 15;
    const int qt = blockIdx.x;
    const uint32_t sb = smem_u32(smem);
    const uint32_t mbQ = sb + 81920, mbF = mbQ + 8;

    // kv block source pointers (element offsets; 128 rows x 64 cols = 8192 elems)
    const __half* Ksrc[7];
    const __half* Vsrc[7];
    {
        const __half* kb = ksh + (size_t)bh * (Tc * 64);
        const __half* vb = vsh + (size_t)bh * (Tc * 64);
        Ksrc[0] = kb;         Vsrc[0] = vb;
        Ksrc[1] = kb + 8192;  Vsrc[1] = vb + 8192;
        const __half* ka = kah + (size_t)bh * (SAc * 64);
        const __half* va = vah + (size_t)bh * (SAc * 64);
        #pragma unroll
        for (int j = 0; j < 4; j++) { Ksrc[2 + j] = ka + j * 8192; Vsrc[2 + j] = va + j * 8192; }
        Ksrc[6] = kth + (size_t)bh * (STc * 64);
        Vsrc[6] = vth + (size_t)bh * (STc * 64);
    }

    auto issue = [&](int slot, int blk) {
        uint32_t kd = sb + 16384 + slot * 32768;
        uint32_t bar = mbF + 8 * slot;
        MBAR_EXPECT(bar, 32768u);
        BULK8K(kd,          Ksrc[blk],        bar);
        BULK8K(kd + 8192,   Ksrc[blk] + 4096, bar);
        BULK8K(kd + 16384,  Vsrc[blk],        bar);
        BULK8K(kd + 24576,  Vsrc[blk] + 4096, bar);
    };

    if (tid == 0) {
        MBAR_INIT(mbQ, 1);
        MBAR_INIT(mbF, 1);
        MBAR_INIT(mbF + 8, 1);
        FENCE_ASYNC();
        MBAR_EXPECT(mbQ, 16384u);
        const __half* qsrc = qh + (size_t)bh * (Tc * 64) + qt * 8192;
        BULK8K(sb,        qsrc,        mbQ);
        BULK8K(sb + 8192, qsrc + 4096, mbQ);
        issue(0, 0);
        issue(1, 1);
    }
    __syncthreads();

    // fragment lane geometry
    const int ra  = (lane & 7) + ((lane >> 3) & 1) * 8;   // A rows
    const int sa  = lane >> 4;                             // A k-half
    const int rbn = (lane & 7) + (lane >> 4) * 8;          // B(non-trans) rows
    const int sbk = (lane >> 3) & 1;                       // B k-half
    const int rvk = (lane & 7) + ((lane >> 3) & 1) * 8;    // V trans: k row
    const int svd = (lane >> 4) & 1;                       // V trans: d-half

    MBAR_WAIT(mbQ, 0);
    uint32_t qa[4][4];
    #pragma unroll
    for (int ks = 0; ks < 4; ks++)
        LDSM4(qa[ks], sb + 2 * (uint32_t)tile_off(16 * w + ra, ks * 16 + sa * 8, 64));

    float sO[8][4];
    #pragma unroll
    for (int i = 0; i < 8; i++)
        #pragma unroll
        for (int e = 0; e < 4; e++) sO[i][e] = 0.f;
    float m0 = -1e30f, m1 = -1e30f, l0 = 0.f, l1 = 0.f;

    for (int blk = 0; blk < 7; blk++) {
        const int slot = blk & 1;
        MBAR_WAIT(mbF + 8 * slot, (blk >> 1) & 1);
        const uint32_t kbase = sb + 16384 + slot * 32768;
        const uint32_t vbase = kbase + 16384;

        float sc[16][4];
        #pragma unroll
        for (int i = 0; i < 16; i++)
            #pragma unroll
            for (int e = 0; e < 4; e++) sc[i][e] = 0.f;

        #pragma unroll
        for (int ks = 0; ks < 4; ks++) {
            #pragma unroll
            for (int np = 0; np < 8; np++) {
                uint32_t b4[4];
                LDSM4(b4, kbase + 2 * (uint32_t)tile_off(16 * np + rbn, ks * 16 + sbk * 8, 64));
                mma_f16(sc[2 * np],     qa[ks], &b4[0]);
                mma_f16(sc[2 * np + 1], qa[ks], &b4[2]);
            }
        }

        float tm0 = -1e30f, tm1 = -1e30f;
        #pragma unroll
        for (int i = 0; i < 16; i++) {
            tm0 = fmaxf(tm0, fmaxf(sc[i][0], sc[i][1]));
            tm1 = fmaxf(tm1, fmaxf(sc[i][2], sc[i][3]));
        }
        tm0 = fmaxf(tm0, __shfl_xor_sync(0xffffffffu, tm0, 1));
        tm0 = fmaxf(tm0, __shfl_xor_sync(0xffffffffu, tm0, 2));
        tm1 = fmaxf(tm1, __shfl_xor_sync(0xffffffffu, tm1, 1));
        tm1 = fmaxf(tm1, __shfl_xor_sync(0xffffffffu, tm1, 2));
        float nm0 = fmaxf(m0, tm0), nm1 = fmaxf(m1, tm1);
        float cr0 = __expf(m0 - nm0), cr1 = __expf(m1 - nm1);
        l0 *= cr0; l1 *= cr1;
        #pragma unroll
        for (int i = 0; i < 8; i++) {
            sO[i][0] *= cr0; sO[i][1] *= cr0;
            sO[i][2] *= cr1; sO[i][3] *= cr1;
        }
        m0 = nm0; m1 = nm1;

        uint32_t pf[16][2];
        #pragma unroll
        for (int i = 0; i < 16; i++) {
            float p0 = __expf(sc[i][0] - nm0), p1 = __expf(sc[i][1] - nm0);
            float p2 = __expf(sc[i][2] - nm1), p3 = __expf(sc[i][3] - nm1);
            l0 += p0 + p1;
            l1 += p2 + p3;
            __half2 h0 = __floats2half2_rn(p0, p1), h1 = __floats2half2_rn(p2, p3);
            pf[i][0] = *(uint32_t*)&h0;
            pf[i][1] = *(uint32_t*)&h1;
        }

        #pragma unroll
        for (int u = 0; u < 8; u++) {
            uint32_t pa[4] = {pf[2*u][0], pf[2*u][1], pf[2*u+1][0], pf[2*u+1][1]};
            #pragma unroll
            for (int nd = 0; nd < 4; nd++) {
                uint32_t vb4[4];
                LDSM4T(vb4, vbase + 2 * (uint32_t)tile_off(16 * u + rvk, 16 * nd + svd * 8, 64));
                mma_f16(sO[2 * nd],     pa, &vb4[0]);
                mma_f16(sO[2 * nd + 1], pa, &vb4[2]);
            }
        }
        __syncthreads();
        if (tid == 0 && blk + 2 < 7) { FENCE_ASYNC(); issue(slot, blk + 2); }
    }

    l0 += __shfl_xor_sync(0xffffffffu, l0, 1);
    l0 += __shfl_xor_sync(0xffffffffu, l0, 2);
    l1 += __shfl_xor_sync(0xffffffffu, l1, 1);
    l1 += __shfl_xor_sync(0xffffffffu, l1, 2);
    float i0 = 1.f / l0, i1 = 1.f / l1;

    int orow = b * Tc + qt * 128 + 16 * w + g;
    #pragma unroll
    for (int nt = 0; nt < 8; nt++) {
        int col = h * 64 + nt * 8 + 2 * t;
        __half2 v0 = __floats2half2_rn(sO[nt][0] * i0, sO[nt][1] * i0);
        __half2 v1 = __floats2half2_rn(sO[nt][2] * i1, sO[nt][3] * i1);
        *(__half2*)(oh + tile_off(orow, col, Dc))     = v0;
        *(__half2*)(oh + tile_off(orow + 8, col, Dc)) = v1;
    }
}

__global__ void final_kernel(const float* __restrict__ x, const float* __restrict__ lw,
                             const float* __restrict__ lb, const float* __restrict__ Wout,
                             const float* __restrict__ bout, float* __restrict__ out) {
    __shared__ float red[256];
    int row = blockIdx.x, tid = threadIdx.x;
    const float* xr = x + (size_t)row * Dc;
    float v[4], s = 0.f;
    #pragma unroll
    for (int i = 0; i < 4; i++) { v[i] = xr[tid + i * 256]; s += v[i]; }
    float mean = block_reduce_sum(s, red) * (1.f / 1024.f);
    float sq = 0.f;
    #pragma unroll
    for (int i = 0; i < 4; i++) { float d = v[i] - mean; sq += d * d; }
    float rstd = rsqrtf(block_reduce_sum(sq, red) * (1.f / 1024.f) + 1e-5f);
    float p0 = 0.f, p1 = 0.f, p2 = 0.f;
    #pragma unroll
    for (int i = 0; i < 4; i++) {
        int d = tid + i * 256;
        float y = (v[i] - mean) * rstd * lw[d] + lb[d];
        p0 = fmaf(y, Wout[d * OUTc + 0], p0);
        p1 = fmaf(y, Wout[d * OUTc + 1], p1);
        p2 = fmaf(y, Wout[d * OUTc + 2], p2);
    }
    p0 = block_reduce_sum(p0, red);
    p1 = block_reduce_sum(p1, red);
    p2 = block_reduce_sum(p2, red);
    if (tid == 0) {
        out[row * OUTc + 0] = p0 + bout[0];
        out[row * OUTc + 1] = p1 + bout[1];
        out[row * OUTc + 2] = p2 + bout[2];
    }
}

extern "C" void kernel_launch(void* const* d_in, const int* in_sizes, int n_in,
                              void* d_out, int out_size)
{
    (void)in_sizes; (void)n_in; (void)out_size;
    const float* x    = (const float*)d_in[0];
    const float* cond = (const float*)d_in[1];
    const float* adp  = (const float*)d_in[2];
    const float* task = (const float*)d_in[3];
    const float* Wq   = (const float*)d_in[4];
    const float* bq   = (const float*)d_in[5];
    const float* Wks  = (const float*)d_in[6];
    const float* Wvs  = (const float*)d_in[7];
    const float* Wka  = (const float*)d_in[8];
    const float* Wva  = (const float*)d_in[9];
    const float* Wkt  = (const float*)d_in[10];
    const float* Wvt  = (const float*)d_in[11];
    const float* Wo   = (const float*)d_in[12];
    const float* bo   = (const float*)d_in[13];
    const float* qnw  = (const float*)d_in[14];
    const float* knw  = (const float*)d_in[15];
    const float* gate = (const float*)d_in[16];
    const float* Wada = (const float*)d_in[17];
    const float* bada = (const float*)d_in[18];
    const float* W1   = (const float*)d_in[19];
    const float* b1   = (const float*)d_in[20];
    const float* W2   = (const float*)d_in[21];
    const float* b2   = (const float*)d_in[22];
    const float* lnfw = (const float*)d_in[23];
    const float* lnfb = (const float*)d_in[24];
    const float* Wout = (const float*)d_in[25];
    const float* bout = (const float*)d_in[26];
    float* out = (float*)d_out;

    cudaFuncSetAttribute(mma_gemm<0>, cudaFuncAttributeMaxDynamicSharedMemorySize, GSMEM);
    cudaFuncSetAttribute(mma_gemm<1>, cudaFuncAttributeMaxDynamicSharedMemorySize, GSMEM);
    cudaFuncSetAttribute(mma_gemm<2>, cudaFuncAttributeMaxDynamicSharedMemorySize, GSMEM);
    cudaFuncSetAttribute(mma_gemm<3>, cudaFuncAttributeMaxDynamicSharedMemorySize, GSMEM);
    cudaFuncSetAttribute(flash_mma,   cudaFuncAttributeMaxDynamicSharedMemorySize, FSMEM);

    float *px, *pq, *pks, *pka, *pkt, *pada, *psc;
    __half *ph, *po, *pf, *pa, *pt, *pw;
    __half *pqh, *pksh, *pvsh, *pkah, *pvah, *pkth, *pvth;
    cudaGetSymbolAddress((void**)&px,  g_x);
    cudaGetSymbolAddress((void**)&pq,  g_q);
    cudaGetSymbolAddress((void**)&pks, g_ks);
    cudaGetSymbolAddress((void**)&pka, g_ka);
    cudaGetSymbolAddress((void**)&pkt, g_kt);
    cudaGetSymbolAddress((void**)&pada, g_ada);
    cudaGetSymbolAddress((void**)&psc,  g_sc);
    cudaGetSymbolAddress((void**)&ph, g_h);
    cudaGetSymbolAddress((void**)&po, g_o);
    cudaGetSymbolAddress((void**)&pf, g_ff);
    cudaGetSymbolAddress((void**)&pa, g_adp);
    cudaGetSymbolAddress((void**)&pt, g_tsk);
    cudaGetSymbolAddress((void**)&pw, g_w);
    cudaGetSymbolAddress((void**)&pqh,  g_qh);
    cudaGetSymbolAddress((void**)&pksh, g_ksh);
    cudaGetSymbolAddress((void**)&pvsh, g_vsh);
    cudaGetSymbolAddress((void**)&pkah, g_kah);
    cudaGetSymbolAddress((void**)&pvah, g_vah);
    cudaGetSymbolAddress((void**)&pkth, g_kth);
    cudaGetSymbolAddress((void**)&pvth, g_vth);

    copy_kernel<<<(MTc*Dc)/256, 256>>>(x, px, MTc*Dc);
    silu_kernel<<<(Bc*Dc)/256, 256>>>(cond, psc, Bc*Dc);
    split_tile<<<(MAc*Dc)/256, 256>>>(adp,  pa);
    split_tile<<<(MSc*Dc)/256, 256>>>(task, pt);

    const float* wsrc[8] = {Wq, Wks, Wvs, Wka, Wva, Wkt, Wvt, Wo};
    for (int i = 0; i < Lc; i++) {
        size_t base = (size_t)i * WPLc;
        for (int mtx = 0; mtx < 8; mtx++)
            wprep<<<dim3(Dc/128, Dc/32), 256>>>(
                wsrc[mtx] + (size_t)i * DDc, pw + base + (size_t)mtx * DDc, Dc, Dc);
        wprep<<<dim3(DFFc/128, Dc/32), 256>>>(
            W1 + (size_t)i * Dc * DFFc, pw + base + 8*DDc, Dc, DFFc);
        wprep<<<dim3(Dc/128, DFFc/32), 256>>>(
            W2 + (size_t)i * DFFc * Dc, pw + base + 8*DDc + (size_t)Dc*DFFc, DFFc, Dc);
    }

    for (int i = 0; i < Lc; i++) {
        size_t wb = (size_t)i * WPLc;
        __half *wv[8];
        for (int m = 0; m < 8; m++) wv[m] = pw + wb + (size_t)m*DDc;
        __half* w1 = pw + wb + 8*(size_t)DDc;
        __half* w2 = pw + wb + 8*(size_t)DDc + (size_t)Dc*DFFc;

        small_gemm_kernel<<<dim3((6*Dc)/256, Bc), 256>>>(
            psc, Wada + (size_t)i*Dc*6*Dc, bada + (size_t)i*6*Dc, pada, 6*Dc, Dc);

        ln_mod<<<MTc, 256>>>(px, pada, 0, Dc, ph);

        // Q/K projections -> fp32 (rmsrope follows); V projections -> fp16 per-(b,h) direct
        mma_gemm<0><<<dim3(Dc/128, MTc/128), 256, GSMEM>>>(ph, wv[0], bq + (size_t)i*Dc, pq,  MTc, Dc, Dc, nullptr, 0, nullptr, nullptr, 0);
        mma_gemm<0><<<dim3(Dc/128, MTc/128), 256, GSMEM>>>(ph, wv[1], nullptr, pks, MTc, Dc, Dc, nullptr, 0, nullptr, nullptr, 0);
        mma_gemm<3><<<dim3(Dc/128, MTc/128), 256, GSMEM>>>(ph, wv[2], nullptr, nullptr, MTc, Dc, Dc, nullptr, 0, nullptr, pvsh, 8);
        mma_gemm<0><<<dim3(Dc/128, MAc/128), 256, GSMEM>>>(pa, wv[3], nullptr, pka, MAc, Dc, Dc, nullptr, 0, nullptr, nullptr, 0);
        mma_gemm<3><<<dim3(Dc/128, MAc/128), 256, GSMEM>>>(pa, wv[4], nullptr, nullptr, MAc, Dc, Dc, nullptr, 0, nullptr, pvah, 9);
        mma_gemm<0><<<dim3(Dc/128, MSc/128), 256, GSMEM>>>(pt, wv[5], nullptr, pkt, MSc, Dc, Dc, nullptr, 0, nullptr, nullptr, 0);
        mma_gemm<3><<<dim3(Dc/128, MSc/128), 256, GSMEM>>>(pt, wv[6], nullptr, nullptr, MSc, Dc, Dc, nullptr, 0, nullptr, pvth, 7);

        rmsrope_h<<<(MTc*Hc*32)/256, 256>>>(pq,  qnw + (size_t)i*HDc, 8, 0.125f, nullptr, pqh);
        rmsrope_h<<<(MTc*Hc*32)/256, 256>>>(pks, knw + (size_t)i*HDc, 8, 1.f,    nullptr, pksh);
        rmsrope_h<<<(MAc*Hc*32)/256, 256>>>(pka, knw + (size_t)i*HDc, 9, 1.f,    nullptr, pkah);
        rmsrope_h<<<(MSc*Hc*32)/256, 256>>>(pkt, knw + (size_t)i*HDc, 7, 1.f,    gate + i, pkth);

        flash_mma<<<dim3(Tc/128, Bc*Hc), 256, FSMEM>>>(pqh, pksh, pvsh, pkah, pvah, pkth, pvth, po);

        mma_gemm<2><<<dim3(Dc/128, MTc/128), 256, GSMEM>>>(po, wv[7], bo + (size_t)i*Dc, nullptr,
                                                           MTc, Dc, Dc, pada + 2*Dc, 6*Dc, px, nullptr, 0);

        ln_mod<<<MTc, 256>>>(px, pada, 3*Dc, 4*Dc, ph);

        mma_gemm<1><<<dim3(DFFc/128, MTc/128), 256, GSMEM>>>(ph, w1, b1 + (size_t)i*DFFc, nullptr,
                                                             MTc, DFFc, Dc, nullptr, 0, nullptr, pf, 0);

        mma_gemm<2><<<dim3(Dc/128, MTc/128), 256, GSMEM>>>(pf, w2, b2 + (size_t)i*Dc, nullptr,
                                                           MTc, Dc, DFFc, pada + 5*Dc, 6*Dc, px, nullptr, 0);
    }

    final_kernel<<<MTc, 256>>>(px, lnfw, lnfb, Wout, bout, out);
}